// round 14
// baseline (speedup 1.0000x reference)
#include <cuda_runtime.h>
#include <cuda_fp16.h>
#include <cstdint>
#include <cstddef>

#define S_LEN 2048
#define DIM   2048
#define HEADS 16
#define HD    128
#define BATCH 4

// Scratch (allocation-free rule: __device__ globals)
#define PLANE_ELEMS ((size_t)BATCH * HEADS * S_LEN * HD)
__device__ __half g_qh[PLANE_ELEMS];
__device__ __half g_kh[PLANE_ELEMS];
__device__ __half g_vh[PLANE_ELEMS];
__device__ __half g_xh[(size_t)BATCH * S_LEN * DIM];
__device__ __half g_ah[(size_t)BATCH * S_LEN * DIM];
__device__ __half g_wqh[(size_t)(3 * DIM) * DIM];
__device__ __half g_woh[(size_t)DIM * DIM];

// ---------------------------------------------------------------------------
// helpers
// ---------------------------------------------------------------------------
__device__ __forceinline__ uint32_t smem_to_u32(const void* p) {
    uint32_t a;
    asm("{ .reg .u64 t; cvta.to.shared.u64 t, %1; cvt.u32.u64 %0, t; }"
        : "=r"(a) : "l"(p));
    return a;
}

__device__ __forceinline__ void ldsm4(uint32_t* r, uint32_t addr) {
    asm volatile("ldmatrix.sync.aligned.m8n8.x4.shared.b16 {%0,%1,%2,%3}, [%4];"
                 : "=r"(r[0]), "=r"(r[1]), "=r"(r[2]), "=r"(r[3]) : "r"(addr));
}

__device__ __forceinline__ void ldsm4t(uint32_t* r, uint32_t addr) {
    asm volatile("ldmatrix.sync.aligned.m8n8.x4.trans.shared.b16 {%0,%1,%2,%3}, [%4];"
                 : "=r"(r[0]), "=r"(r[1]), "=r"(r[2]), "=r"(r[3]) : "r"(addr));
}

__device__ __forceinline__ void mma_f16(float* d, const uint32_t* a, const uint32_t* b) {
    asm volatile(
        "mma.sync.aligned.m16n8k16.row.col.f32.f16.f16.f32 "
        "{%0,%1,%2,%3}, {%4,%5,%6,%7}, {%8,%9}, {%0,%1,%2,%3};"
        : "+f"(d[0]), "+f"(d[1]), "+f"(d[2]), "+f"(d[3])
        : "r"(a[0]), "r"(a[1]), "r"(a[2]), "r"(a[3]), "r"(b[0]), "r"(b[1]));
}

// pack (x0,x1) -> fp16x2 (low half = x0)
__device__ __forceinline__ uint32_t packh2(float x0, float x1) {
    __half2 h = __floats2half2_rn(x0, x1);
    return *(uint32_t*)&h;
}

#define CP_ASYNC16(dst, src) \
    asm volatile("cp.async.cg.shared.global [%0], [%1], 16;" \
                 :: "r"(dst), "l"(src) : "memory")
#define CP_COMMIT() asm volatile("cp.async.commit_group;" ::: "memory")
#define CP_WAIT1()  asm volatile("cp.async.wait_group 1;" ::: "memory")

// ---------------------------------------------------------------------------
// Elementwise round: fp32 -> fp16 plane
// ---------------------------------------------------------------------------
__global__ __launch_bounds__(256) void round_kernel(
    const float* __restrict__ in, __half* __restrict__ out, size_t n2)
{
    size_t i = (size_t)blockIdx.x * blockDim.x + threadIdx.x;
    size_t stride = (size_t)gridDim.x * blockDim.x;
    for (; i < n2; i += stride) {
        float2 v = *(const float2*)(in + 2 * i);
        *(uint32_t*)(out + 2 * i) = packh2(v.x, v.y);
    }
}

// ---------------------------------------------------------------------------
// Transpose + round: fp32 in[R][C] -> fp16 out[C][R]
// ---------------------------------------------------------------------------
__global__ __launch_bounds__(256) void transpose_round_kernel(
    const float* __restrict__ in, __half* __restrict__ out, int R, int C)
{
    __shared__ float t[32][33];
    int bx = blockIdx.x * 32;
    int by = blockIdx.y * 32;
    int x = threadIdx.x, y = threadIdx.y;   // 32 x 8
#pragma unroll
    for (int j = 0; j < 32; j += 8)
        t[y + j][x] = in[(size_t)(by + y + j) * C + bx + x];
    __syncthreads();
#pragma unroll
    for (int jj = 0; jj < 2; jj++) {
        int cp = y + 8 * jj;                 // 0..15 col pair index
        uint32_t h = packh2(t[cp * 2][x], t[cp * 2 + 1][x]);
        size_t o = (size_t)(bx + x) * R + by + cp * 2;
        *(uint32_t*)(out + o) = h;
    }
}

// ---------------------------------------------------------------------------
// fp16 single-product GEMM (measured-best config): C = Ah @ Bh^T (+bias).
// 128x128 tile, BK=64, 256 threads = 8 warps (4x2), warp tile 32x64.
// 3-stage cp.async pipeline, 2 CTAs/SM.
// ---------------------------------------------------------------------------
#define GSTRIDE      144
#define GB_OFF       18432
#define GSTAGE_BYTES 36864
#define GSMEM_BYTES  (3 * GSTAGE_BYTES)

#define GEMM1_BODY                                                            \
    extern __shared__ __align__(1024) char smem[];                            \
    const uint32_t sb = smem_to_u32(smem);                                    \
    const int tid = threadIdx.x;                                              \
    const int wid = tid >> 5, lid = tid & 31;                                 \
    const int wm = wid >> 1;                                                  \
    const int wn = wid & 1;                                                   \
    const uint32_t aBase = (uint32_t)((wm * 32 + (lid & 15)) * GSTRIDE + (lid >> 4) * 16); \
    const uint32_t bBase = (uint32_t)((wn * 64 + ((lid >> 1) & 8) + (lid & 7)) * GSTRIDE \
                                      + ((lid & 8) << 1));                    \
    float acc[2][8][4];                                                       \
    _Pragma("unroll")                                                         \
    for (int mf = 0; mf < 2; mf++)                                            \
        _Pragma("unroll")                                                     \
        for (int nf = 0; nf < 8; nf++)                                        \
            _Pragma("unroll")                                                 \
            for (int q = 0; q < 4; q++) acc[mf][nf][q] = 0.f;                 \
    const int niter = K >> 6;                                                 \
    auto issue = [&](int i, int s) {                                          \
        const int k0 = i << 6;                                                \
        const uint32_t base = sb + s * GSTAGE_BYTES;                          \
        _Pragma("unroll")                                                     \
        for (int j = 0; j < 4; j++) {                                         \
            int c = tid + 256 * j;                                            \
            int row = c >> 3, c8 = c & 7;                                     \
            uint32_t so = (uint32_t)(row * GSTRIDE + c8 * 16);                \
            CP_ASYNC16(base + so,          (const char*)(Ah + (size_t)(m0 + row) * K + k0 + c8 * 8)); \
            CP_ASYNC16(base + GB_OFF + so, (const char*)(Bh + (size_t)(n0 + row) * K + k0 + c8 * 8)); \
        }                                                                     \
    };                                                                        \
    issue(0, 0); CP_COMMIT();                                                 \
    if (niter > 1) { issue(1, 1); CP_COMMIT(); }                              \
    for (int i = 0; i < niter; i++) {                                         \
        const int s = i % 3;                                                  \
        CP_WAIT1();                                                           \
        __syncthreads();                                                      \
        if (i + 2 < niter) issue(i + 2, (i + 2) % 3);                         \
        CP_COMMIT();                                                          \
        const uint32_t sA = sb + s * GSTAGE_BYTES;                            \
        _Pragma("unroll")                                                     \
        for (int kstep = 0; kstep < 4; kstep++) {                             \
            const uint32_t koff = kstep * 32;                                 \
            uint32_t ah[2][4];                                                \
            ldsm4(ah[0], sA + aBase + koff);                                  \
            ldsm4(ah[1], sA + aBase + 16 * GSTRIDE + koff);                   \
            uint32_t bh[8][2];                                                \
            _Pragma("unroll")                                                 \
            for (int t2 = 0; t2 < 4; t2++) {                                  \
                uint32_t r[4];                                                \
                ldsm4(r, sA + GB_OFF + bBase + t2 * 16 * GSTRIDE + koff);     \
                bh[2 * t2][0] = r[0]; bh[2 * t2][1] = r[1];                   \
                bh[2 * t2 + 1][0] = r[2]; bh[2 * t2 + 1][1] = r[3];           \
            }                                                                 \
            _Pragma("unroll")                                                 \
            for (int mf = 0; mf < 2; mf++)                                    \
                _Pragma("unroll")                                             \
                for (int nf = 0; nf < 8; nf++)                                \
                    mma_f16(acc[mf][nf], ah[mf], bh[nf]);                     \
        }                                                                     \
    }                                                                         \
    __syncthreads();

// fp32 output GEMM (output projection)
__global__ __launch_bounds__(256, 2) void gemm1_out_kernel(
    const __half* __restrict__ Ah, const __half* __restrict__ Bh,
    const float* __restrict__ bias, float* __restrict__ C, int N, int K)
{
    const int m0 = blockIdx.y * 128;
    const int n0 = blockIdx.x * 128;
    GEMM1_BODY
    const int erow = m0 + wm * 32 + (lid >> 2);
    const int ecol0 = n0 + wn * 64 + (lid & 3) * 2;
#pragma unroll
    for (int mf = 0; mf < 2; mf++) {
#pragma unroll
        for (int nf = 0; nf < 8; nf++) {
            int col = ecol0 + nf * 8;
            float2 bz = *(const float2*)(bias + col);
            float2 v0, v1;
            v0.x = acc[mf][nf][0] + bz.x; v0.y = acc[mf][nf][1] + bz.y;
            v1.x = acc[mf][nf][2] + bz.x; v1.y = acc[mf][nf][3] + bz.y;
            size_t r0 = (size_t)(erow + mf * 16) * N + col;
            *(float2*)(C + r0) = v0;
            *(float2*)(C + r0 + 8 * N) = v1;
        }
    }
}

// QKV GEMM: single product -> single fp16 plane (Q pre-scaled)
__global__ __launch_bounds__(256, 2) void gemm1_qkv_kernel(
    const __half* __restrict__ Ah, const __half* __restrict__ Bh,
    const float* __restrict__ bias,
    __half* __restrict__ qh, __half* __restrict__ kh, __half* __restrict__ vh,
    int N, int K)
{
    const int m0 = blockIdx.y * 128;
    const int n0 = blockIdx.x * 128;
    GEMM1_BODY
    const int t = n0 >> 11;                 // 0=Q 1=K 2=V
    const int head = (n0 >> 7) & (HEADS - 1);
    __half* p = (t == 0) ? qh : ((t == 1) ? kh : vh);
    const float sc = (t == 0) ? 0.08838834764831845f : 1.0f;
    const int erow = m0 + wm * 32 + (lid >> 2);
    const int lcol0 = wn * 64 + (lid & 3) * 2;
#pragma unroll
    for (int mf = 0; mf < 2; mf++) {
        int tok0 = erow + mf * 16;
        int b = tok0 >> 11;
        int s0 = tok0 & 2047;
        size_t pb = ((size_t)(b * HEADS + head) * S_LEN) * HD;
#pragma unroll
        for (int nf = 0; nf < 8; nf++) {
            int lc = lcol0 + nf * 8;
            float2 bz = *(const float2*)(bias + n0 + lc);
            float v0 = (acc[mf][nf][0] + bz.x) * sc;
            float v1 = (acc[mf][nf][1] + bz.y) * sc;
            float v2 = (acc[mf][nf][2] + bz.x) * sc;
            float v3 = (acc[mf][nf][3] + bz.y) * sc;
            *(uint32_t*)(p + pb + (size_t)s0 * HD + lc)       = packh2(v0, v1);
            *(uint32_t*)(p + pb + (size_t)(s0 + 8) * HD + lc) = packh2(v2, v3);
        }
    }
}

// ---------------------------------------------------------------------------
// Tensor-core flash attention (fp16), Q tile = 256 rows, warp = 32 q-rows.
// 3-stage K/V cp.async pipeline, one barrier per tile, per-warp full-skip
// and mask-free fast path. grid (8, HEADS, BATCH), 256 threads = 8 warps.
// ---------------------------------------------------------------------------
#define AQ_STRIDE 272                 // smem bytes per row (128 fp16 + pad)
#define SQH 0                         // 256 * 272 = 69632
#define SSTAGE0 69632
#define SSTAGE_BYTES 34816            // Kh (17408) + Vh (17408)
#define SKH 0
#define SVH 17408
#define SKID  174080                  // + stage*256 (3 stages)
#define ATTN_SMEM 174848

__global__ __launch_bounds__(256, 1) void attn_mma_kernel(
    const int* __restrict__ ids,
    __half* __restrict__ oh,
    const __half* __restrict__ qh,
    const __half* __restrict__ kh, const __half* __restrict__ vh)
{
    extern __shared__ __align__(1024) char smem[];
    const uint32_t sb = smem_to_u32(smem);
    const int tid = threadIdx.x;
    const int lane = tid & 31, wid = tid >> 5;
    const int b = blockIdx.z, h = blockIdx.y;
    const int qt = gridDim.x - 1 - blockIdx.x;       // big tiles first
    const int q0 = qt * 256;
    const size_t pbase = (size_t)(b * HEADS + h) * S_LEN * HD;
    const int* bids = ids + b * S_LEN;

    const int lr = lane >> 2;
    const int qw0 = q0 + wid * 32;                   // warp's first q row
    int qrow[2][2], qidv[2][2];
#pragma unroll
    for (int mf = 0; mf < 2; mf++) {
        qrow[mf][0] = qw0 + mf * 16 + lr;
        qrow[mf][1] = qrow[mf][0] + 8;
        qidv[mf][0] = bids[qrow[mf][0]];
        qidv[mf][1] = bids[qrow[mf][1]];
    }
    const int qid_min = bids[q0];
    const int idq0 = bids[qw0];
    const bool seg_uni_q = (idq0 == bids[qw0 + 31]);

    auto issue_tile = [&](int kb, int s) {
        const int k0 = kb * 64;
        const uint32_t stg = sb + SSTAGE0 + s * SSTAGE_BYTES;
#pragma unroll
        for (int j = 0; j < 4; j++) {
            int q = tid + 256 * j;
            int key = q >> 4, c16 = q & 15;
            uint32_t soff = (uint32_t)(key * AQ_STRIDE + c16 * 16);
            size_t goff = pbase + (size_t)(k0 + key) * HD + c16 * 8;
            CP_ASYNC16(stg + SKH + soff, (const char*)(kh + goff));
            CP_ASYNC16(stg + SVH + soff, (const char*)(vh + goff));
        }
        if (tid < 16)
            CP_ASYNC16(sb + SKID + s * 256 + tid * 16,
                       (const char*)(bids + k0 + tid * 4));
    };

    const int nkb = 4 * qt + 3;

    // ---- prologue: Q tile (256 rows) + K/V tiles 0,1 ----
#pragma unroll
    for (int j = 0; j < 16; j++) {
        int q = tid + 256 * j;
        int key = q >> 4, c16 = q & 15;
        uint32_t soff = (uint32_t)(key * AQ_STRIDE + c16 * 16);
        size_t goff = pbase + (size_t)(q0 + key) * HD + c16 * 8;
        CP_ASYNC16(sb + SQH + soff, (const char*)(qh + goff));
    }
    if (bids[63] >= qid_min) issue_tile(0, 0);
    CP_COMMIT();
    if (bids[127] >= qid_min) issue_tile(1, 1);
    CP_COMMIT();

    float O[2][16][4];
#pragma unroll
    for (int mf = 0; mf < 2; mf++)
#pragma unroll
        for (int nb = 0; nb < 16; nb++)
#pragma unroll
            for (int q = 0; q < 4; q++) O[mf][nb][q] = 0.f;
    float mR[2][2], lR[2][2];
#pragma unroll
    for (int mf = 0; mf < 2; mf++) {
        mR[mf][0] = -1e30f; mR[mf][1] = -1e30f;
        lR[mf][0] = 0.f; lR[mf][1] = 0.f;
    }

    uint32_t qoffA[2];
#pragma unroll
    for (int mf = 0; mf < 2; mf++)
        qoffA[mf] = (uint32_t)((qw0 - q0 + mf * 16 + (lane & 15)) * AQ_STRIDE
                               + (lane >> 4) * 16);
    const uint32_t kBoff = (uint32_t)((((lane >> 1) & 8) + (lane & 7)) * AQ_STRIDE
                                      + ((lane & 8) << 1));
    const uint32_t vBoff = (uint32_t)((((lane >> 3) & 1) * 8 + (lane & 7)) * AQ_STRIDE
                                      + ((lane >> 4) & 1) * 16);

    for (int kb = 0; kb <= nkb; kb++) {
        const int s = kb % 3;
        CP_WAIT1();
        __syncthreads();
        if (kb + 2 <= nkb) {
            if (bids[(kb + 2) * 64 + 63] >= qid_min) issue_tile(kb + 2, (kb + 2) % 3);
        }
        CP_COMMIT();

        const int k0 = kb * 64;
        const int kidlo = bids[k0];
        const int kidhi = bids[k0 + 63];
        if (kidhi < qid_min || kidhi < idq0) continue;   // CTA/warp full skip

        const uint32_t stg = sb + SSTAGE0 + s * SSTAGE_BYTES;

        // ---- S = Q·K^T over 64 keys, 2 m-frags ----
        float S[2][8][4];
#pragma unroll
        for (int mf = 0; mf < 2; mf++)
#pragma unroll
            for (int nf = 0; nf < 8; nf++)
#pragma unroll
                for (int c = 0; c < 4; c++) S[mf][nf][c] = 0.f;
#pragma unroll
        for (int ks = 0; ks < 8; ks++) {
            uint32_t ah0[4], ah1[4];
            ldsm4(ah0, sb + SQH + qoffA[0] + ks * 32);
            ldsm4(ah1, sb + SQH + qoffA[1] + ks * 32);
#pragma unroll
            for (int kf = 0; kf < 4; kf++) {
                uint32_t khf[4];
                ldsm4(khf, stg + SKH + kBoff + kf * 16 * AQ_STRIDE + ks * 32);
                mma_f16(S[0][2 * kf],     ah0, khf + 0);
                mma_f16(S[0][2 * kf + 1], ah0, khf + 2);
                mma_f16(S[1][2 * kf],     ah1, khf + 0);
                mma_f16(S[1][2 * kf + 1], ah1, khf + 2);
            }
        }

        const bool fast = seg_uni_q && (kidlo == kidhi) && (kidlo == idq0)
                          && (k0 + 63 <= qw0);

        float mt[2][2];
        mt[0][0] = mt[0][1] = mt[1][0] = mt[1][1] = -1e30f;
        if (fast) {
#pragma unroll
            for (int mf = 0; mf < 2; mf++)
#pragma unroll
                for (int nf = 0; nf < 8; nf++) {
                    mt[mf][0] = fmaxf(mt[mf][0], fmaxf(S[mf][nf][0], S[mf][nf][1]));
                    mt[mf][1] = fmaxf(mt[mf][1], fmaxf(S[mf][nf][2], S[mf][nf][3]));
                }
        } else {
            const uint32_t kidb = sb + SKID + s * 256;
#pragma unroll
            for (int nf = 0; nf < 8; nf++) {
                int lc = nf * 8 + 2 * (lane & 3);
                int kv0, kv1;
                asm volatile("ld.shared.v2.u32 {%0,%1}, [%2];"
                             : "=r"(kv0), "=r"(kv1) : "r"(kidb + lc * 4));
                int key = k0 + lc;
#pragma unroll
                for (int mf = 0; mf < 2; mf++) {
                    if (key     > qrow[mf][0] || kv0 != qidv[mf][0]) S[mf][nf][0] = -1e30f;
                    if (key + 1 > qrow[mf][0] || kv1 != qidv[mf][0]) S[mf][nf][1] = -1e30f;
                    if (key     > qrow[mf][1] || kv0 != qidv[mf][1]) S[mf][nf][2] = -1e30f;
                    if (key + 1 > qrow[mf][1] || kv1 != qidv[mf][1]) S[mf][nf][3] = -1e30f;
                    mt[mf][0] = fmaxf(mt[mf][0], fmaxf(S[mf][nf][0], S[mf][nf][1]));
                    mt[mf][1] = fmaxf(mt[mf][1], fmaxf(S[mf][nf][2], S[mf][nf][3]));
                }
            }
        }
#pragma unroll
        for (int mf = 0; mf < 2; mf++)
#pragma unroll
            for (int r = 0; r < 2; r++) {
                float m = mt[mf][r];
                m = fmaxf(m, __shfl_xor_sync(0xffffffffu, m, 1));
                m = fmaxf(m, __shfl_xor_sync(0xffffffffu, m, 2));
                mt[mf][r] = m;
            }

        float fR[2][2];
#pragma unroll
        for (int mf = 0; mf < 2; mf++)
#pragma unroll
            for (int r = 0; r < 2; r++) {
                float mn = fmaxf(mR[mf][r], mt[mf][r]);
                fR[mf][r] = __expf(mR[mf][r] - mn);
                mR[mf][r] = mn;
            }

#pragma unroll
        for (int mf = 0; mf < 2; mf++) {
            float rs0 = 0.f, rs1 = 0.f;
            if (fast) {
#pragma unroll
                for (int nf = 0; nf < 8; nf++) {
                    float p0 = __expf(S[mf][nf][0] - mR[mf][0]);
                    float p1 = __expf(S[mf][nf][1] - mR[mf][0]);
                    float p2 = __expf(S[mf][nf][2] - mR[mf][1]);
                    float p3 = __expf(S[mf][nf][3] - mR[mf][1]);
                    S[mf][nf][0] = p0; S[mf][nf][1] = p1;
                    S[mf][nf][2] = p2; S[mf][nf][3] = p3;
                    rs0 += p0 + p1; rs1 += p2 + p3;
                }
            } else {
#pragma unroll
                for (int nf = 0; nf < 8; nf++) {
                    float p0 = (S[mf][nf][0] < -1e29f) ? 0.f : __expf(S[mf][nf][0] - mR[mf][0]);
                    float p1 = (S[mf][nf][1] < -1e29f) ? 0.f : __expf(S[mf][nf][1] - mR[mf][0]);
                    float p2 = (S[mf][nf][2] < -1e29f) ? 0.f : __expf(S[mf][nf][2] - mR[mf][1]);
                    float p3 = (S[mf][nf][3] < -1e29f) ? 0.f : __expf(S[mf][nf][3] - mR[mf][1]);
                    S[mf][nf][0] = p0; S[mf][nf][1] = p1;
                    S[mf][nf][2] = p2; S[mf][nf][3] = p3;
                    rs0 += p0 + p1; rs1 += p2 + p3;
                }
            }
            rs0 += __shfl_xor_sync(0xffffffffu, rs0, 1);
            rs0 += __shfl_xor_sync(0xffffffffu, rs0, 2);
            rs1 += __shfl_xor_sync(0xffffffffu, rs1, 1);
            rs1 += __shfl_xor_sync(0xffffffffu, rs1, 2);
            lR[mf][0] = lR[mf][0] * fR[mf][0] + rs0;
            lR[mf][1] = lR[mf][1] * fR[mf][1] + rs1;
        }

        // rescale O
#pragma unroll
        for (int mf = 0; mf < 2; mf++)
#pragma unroll
            for (int nb = 0; nb < 16; nb++) {
                O[mf][nb][0] *= fR[mf][0]; O[mf][nb][1] *= fR[mf][0];
                O[mf][nb][2] *= fR[mf][1]; O[mf][nb][3] *= fR[mf][1];
            }

        // ---- O += RN16(P)·V over the 64-key dim (4 k16 chunks) ----
#pragma unroll
        for (int ks2 = 0; ks2 < 4; ks2++) {
            uint32_t ah0[4], ah1[4];
            ah0[0] = packh2(S[0][2 * ks2][0],     S[0][2 * ks2][1]);
            ah0[1] = packh2(S[0][2 * ks2][2],     S[0][2 * ks2][3]);
            ah0[2] = packh2(S[0][2 * ks2 + 1][0], S[0][2 * ks2 + 1][1]);
            ah0[3] = packh2(S[0][2 * ks2 + 1][2], S[0][2 * ks2 + 1][3]);
            ah1[0] = packh2(S[1][2 * ks2][0],     S[1][2 * ks2][1]);
            ah1[1] = packh2(S[1][2 * ks2][2],     S[1][2 * ks2][3]);
            ah1[2] = packh2(S[1][2 * ks2 + 1][0], S[1][2 * ks2 + 1][1]);
            ah1[3] = packh2(S[1][2 * ks2 + 1][2], S[1][2 * ks2 + 1][3]);
            uint32_t ro = vBoff + ks2 * 16 * AQ_STRIDE;
#pragma unroll
            for (int np = 0; np < 4; np++) {
                uint32_t vh0[4], vh1[4];
                ldsm4t(vh0, stg + SVH + ro + (2 * np) * 32);
                ldsm4t(vh1, stg + SVH + ro + (2 * np + 1) * 32);
                int o0 = 4 * np;
                mma_f16(O[0][o0 + 0], ah0, vh0 + 0); mma_f16(O[0][o0 + 1], ah0, vh0 + 2);
                mma_f16(O[0][o0 + 2], ah0, vh1 + 0); mma_f16(O[0][o0 + 3], ah0, vh1 + 2);
                mma_f16(O[1][o0 + 0], ah1, vh0 + 0); mma_f16(O[1][o0 + 1], ah1, vh0 + 2);
                mma_f16(O[1][o0 + 2], ah1, vh1 + 0); mma_f16(O[1][o0 + 3], ah1, vh1 + 2);
            }
        }
    }

    // ---- epilogue: warp-local normalize, write fp16 plane directly ----
#pragma unroll
    for (int mf = 0; mf < 2; mf++) {
        float inv0 = 1.f / lR[mf][0];
        float inv1 = 1.f / lR[mf][1];
        const size_t g0 = ((size_t)b * S_LEN + qrow[mf][0]) * DIM + h * HD;
        const size_t g1 = ((size_t)b * S_LEN + qrow[mf][1]) * DIM + h * HD;
#pragma unroll
        for (int nb = 0; nb < 16; nb++) {
            int col = nb * 8 + 2 * (lane & 3);
            *(uint32_t*)(oh + g0 + col) =
                packh2(O[mf][nb][0] * inv0, O[mf][nb][1] * inv0);
            *(uint32_t*)(oh + g1 + col) =
                packh2(O[mf][nb][2] * inv1, O[mf][nb][3] * inv1);
        }
    }
}

// ---------------------------------------------------------------------------
extern "C" void kernel_launch(void* const* d_in, const int* in_sizes, int n_in,
                              void* d_out, int out_size)
{
    const float* x    = (const float*)d_in[0];   // [4,2048,2048]
    const int*   ids  = (const int*)d_in[1];     // [4,2048]
    const float* Wqkv = (const float*)d_in[2];   // [2048,6144]
    const float* bqkv = (const float*)d_in[3];   // [6144]
    const float* Wo   = (const float*)d_in[4];   // [2048,2048]
    const float* bo   = (const float*)d_in[5];   // [2048]
    float* out = (float*)d_out;

    __half *qh, *kh, *vh, *xh, *ah, *wqh, *woh;
    cudaGetSymbolAddress((void**)&qh, g_qh);
    cudaGetSymbolAddress((void**)&kh, g_kh);
    cudaGetSymbolAddress((void**)&vh, g_vh);
    cudaGetSymbolAddress((void**)&xh, g_xh);
    cudaGetSymbolAddress((void**)&ah, g_ah);
    cudaGetSymbolAddress((void**)&wqh, g_wqh);
    cudaGetSymbolAddress((void**)&woh, g_woh);

    cudaFuncSetAttribute(gemm1_out_kernel,
                         cudaFuncAttributeMaxDynamicSharedMemorySize, GSMEM_BYTES);
    cudaFuncSetAttribute(gemm1_qkv_kernel,
                         cudaFuncAttributeMaxDynamicSharedMemorySize, GSMEM_BYTES);
    cudaFuncSetAttribute(attn_mma_kernel,
                         cudaFuncAttributeMaxDynamicSharedMemorySize, ATTN_SMEM);

    const int M = BATCH * S_LEN;   // 8192

    // 0) round x, round+transpose weights (one-shot)
    round_kernel<<<1184, 256>>>(x, xh, (size_t)M * DIM / 2);
    {
        dim3 blk(32, 8);
        transpose_round_kernel<<<dim3(3 * DIM / 32, DIM / 32), blk>>>(Wqkv, wqh, DIM, 3 * DIM);
        transpose_round_kernel<<<dim3(DIM / 32, DIM / 32), blk>>>(Wo, woh, DIM, DIM);
    }
    // 1) QKV = x @ Wqkv + bqkv -> fp16 planes (Q pre-scaled), single product
    {
        dim3 grid(3 * DIM / 128, M / 128);
        gemm1_qkv_kernel<<<grid, 256, GSMEM_BYTES>>>(
            xh, wqh, bqkv, qh, kh, vh, 3 * DIM, DIM);
    }
    // 2) flash attention -> single fp16 plane (Q tile 256)
    {
        dim3 grid(S_LEN / 256, HEADS, BATCH);
        attn_mma_kernel<<<grid, 256, ATTN_SMEM>>>(ids, ah, qh, kh, vh);
    }
    // 3) out = attn @ Wo + bo  [8192, 2048] fp32, single product
    {
        dim3 grid(DIM / 128, M / 128);
        gemm1_out_kernel<<<grid, 256, GSMEM_BYTES>>>(ah, woh, bo, out, DIM, DIM);
    }
}

// round 15
// speedup vs baseline: 1.0277x; 1.0277x over previous
#include <cuda_runtime.h>
#include <cuda_fp16.h>
#include <cstdint>
#include <cstddef>

#define S_LEN 2048
#define DIM   2048
#define HEADS 16
#define HD    128
#define BATCH 4

// Scratch (allocation-free rule: __device__ globals)
#define PLANE_ELEMS ((size_t)BATCH * HEADS * S_LEN * HD)
__device__ __half g_qh[PLANE_ELEMS];
__device__ __half g_kh[PLANE_ELEMS];
__device__ __half g_vh[PLANE_ELEMS];
__device__ __half g_xh[(size_t)BATCH * S_LEN * DIM];
__device__ __half g_ah[(size_t)BATCH * S_LEN * DIM];
__device__ __half g_wqh[(size_t)(3 * DIM) * DIM];
__device__ __half g_woh[(size_t)DIM * DIM];

// ---------------------------------------------------------------------------
// helpers
// ---------------------------------------------------------------------------
__device__ __forceinline__ uint32_t smem_to_u32(const void* p) {
    uint32_t a;
    asm("{ .reg .u64 t; cvta.to.shared.u64 t, %1; cvt.u32.u64 %0, t; }"
        : "=r"(a) : "l"(p));
    return a;
}

__device__ __forceinline__ void ldsm4(uint32_t* r, uint32_t addr) {
    asm volatile("ldmatrix.sync.aligned.m8n8.x4.shared.b16 {%0,%1,%2,%3}, [%4];"
                 : "=r"(r[0]), "=r"(r[1]), "=r"(r[2]), "=r"(r[3]) : "r"(addr));
}

__device__ __forceinline__ void ldsm4t(uint32_t* r, uint32_t addr) {
    asm volatile("ldmatrix.sync.aligned.m8n8.x4.trans.shared.b16 {%0,%1,%2,%3}, [%4];"
                 : "=r"(r[0]), "=r"(r[1]), "=r"(r[2]), "=r"(r[3]) : "r"(addr));
}

__device__ __forceinline__ void mma_f16(float* d, const uint32_t* a, const uint32_t* b) {
    asm volatile(
        "mma.sync.aligned.m16n8k16.row.col.f32.f16.f16.f32 "
        "{%0,%1,%2,%3}, {%4,%5,%6,%7}, {%8,%9}, {%0,%1,%2,%3};"
        : "+f"(d[0]), "+f"(d[1]), "+f"(d[2]), "+f"(d[3])
        : "r"(a[0]), "r"(a[1]), "r"(a[2]), "r"(a[3]), "r"(b[0]), "r"(b[1]));
}

// pack (x0,x1) -> fp16x2 (low half = x0)
__device__ __forceinline__ uint32_t packh2(float x0, float x1) {
    __half2 h = __floats2half2_rn(x0, x1);
    return *(uint32_t*)&h;
}

#define CP_ASYNC16(dst, src) \
    asm volatile("cp.async.cg.shared.global [%0], [%1], 16;" \
                 :: "r"(dst), "l"(src) : "memory")
#define CP_COMMIT() asm volatile("cp.async.commit_group;" ::: "memory")
#define CP_WAIT1()  asm volatile("cp.async.wait_group 1;" ::: "memory")

// ---------------------------------------------------------------------------
// Elementwise round: fp32 -> fp16 plane
// ---------------------------------------------------------------------------
__global__ __launch_bounds__(256) void round_kernel(
    const float* __restrict__ in, __half* __restrict__ out, size_t n2)
{
    size_t i = (size_t)blockIdx.x * blockDim.x + threadIdx.x;
    size_t stride = (size_t)gridDim.x * blockDim.x;
    for (; i < n2; i += stride) {
        float2 v = *(const float2*)(in + 2 * i);
        *(uint32_t*)(out + 2 * i) = packh2(v.x, v.y);
    }
}

// ---------------------------------------------------------------------------
// Transpose + round: fp32 in[R][C] -> fp16 out[C][R]
// ---------------------------------------------------------------------------
__global__ __launch_bounds__(256) void transpose_round_kernel(
    const float* __restrict__ in, __half* __restrict__ out, int R, int C)
{
    __shared__ float t[32][33];
    int bx = blockIdx.x * 32;
    int by = blockIdx.y * 32;
    int x = threadIdx.x, y = threadIdx.y;   // 32 x 8
#pragma unroll
    for (int j = 0; j < 32; j += 8)
        t[y + j][x] = in[(size_t)(by + y + j) * C + bx + x];
    __syncthreads();
#pragma unroll
    for (int jj = 0; jj < 2; jj++) {
        int cp = y + 8 * jj;                 // 0..15 col pair index
        uint32_t h = packh2(t[cp * 2][x], t[cp * 2 + 1][x]);
        size_t o = (size_t)(bx + x) * R + by + cp * 2;
        *(uint32_t*)(out + o) = h;
    }
}

// ---------------------------------------------------------------------------
// fp16 single-product GEMM (measured-best config): C = Ah @ Bh^T (+bias).
// 128x128 tile, BK=64, 256 threads = 8 warps (4x2), warp tile 32x64.
// 3-stage cp.async pipeline, 2 CTAs/SM.
// ---------------------------------------------------------------------------
#define GSTRIDE      144
#define GB_OFF       18432
#define GSTAGE_BYTES 36864
#define GSMEM_BYTES  (3 * GSTAGE_BYTES)

#define GEMM1_BODY                                                            \
    extern __shared__ __align__(1024) char smem[];                            \
    const uint32_t sb = smem_to_u32(smem);                                    \
    const int tid = threadIdx.x;                                              \
    const int wid = tid >> 5, lid = tid & 31;                                 \
    const int wm = wid >> 1;                                                  \
    const int wn = wid & 1;                                                   \
    const uint32_t aBase = (uint32_t)((wm * 32 + (lid & 15)) * GSTRIDE + (lid >> 4) * 16); \
    const uint32_t bBase = (uint32_t)((wn * 64 + ((lid >> 1) & 8) + (lid & 7)) * GSTRIDE \
                                      + ((lid & 8) << 1));                    \
    float acc[2][8][4];                                                       \
    _Pragma("unroll")                                                         \
    for (int mf = 0; mf < 2; mf++)                                            \
        _Pragma("unroll")                                                     \
        for (int nf = 0; nf < 8; nf++)                                        \
            _Pragma("unroll")                                                 \
            for (int q = 0; q < 4; q++) acc[mf][nf][q] = 0.f;                 \
    const int niter = K >> 6;                                                 \
    auto issue = [&](int i, int s) {                                          \
        const int k0 = i << 6;                                                \
        const uint32_t base = sb + s * GSTAGE_BYTES;                          \
        _Pragma("unroll")                                                     \
        for (int j = 0; j < 4; j++) {                                         \
            int c = tid + 256 * j;                                            \
            int row = c >> 3, c8 = c & 7;                                     \
            uint32_t so = (uint32_t)(row * GSTRIDE + c8 * 16);                \
            CP_ASYNC16(base + so,          (const char*)(Ah + (size_t)(m0 + row) * K + k0 + c8 * 8)); \
            CP_ASYNC16(base + GB_OFF + so, (const char*)(Bh + (size_t)(n0 + row) * K + k0 + c8 * 8)); \
        }                                                                     \
    };                                                                        \
    issue(0, 0); CP_COMMIT();                                                 \
    if (niter > 1) { issue(1, 1); CP_COMMIT(); }                              \
    for (int i = 0; i < niter; i++) {                                         \
        const int s = i % 3;                                                  \
        CP_WAIT1();                                                           \
        __syncthreads();                                                      \
        if (i + 2 < niter) issue(i + 2, (i + 2) % 3);                         \
        CP_COMMIT();                                                          \
        const uint32_t sA = sb + s * GSTAGE_BYTES;                            \
        _Pragma("unroll")                                                     \
        for (int kstep = 0; kstep < 4; kstep++) {                             \
            const uint32_t koff = kstep * 32;                                 \
            uint32_t ah[2][4];                                                \
            ldsm4(ah[0], sA + aBase + koff);                                  \
            ldsm4(ah[1], sA + aBase + 16 * GSTRIDE + koff);                   \
            uint32_t bh[8][2];                                                \
            _Pragma("unroll")                                                 \
            for (int t2 = 0; t2 < 4; t2++) {                                  \
                uint32_t r[4];                                                \
                ldsm4(r, sA + GB_OFF + bBase + t2 * 16 * GSTRIDE + koff);     \
                bh[2 * t2][0] = r[0]; bh[2 * t2][1] = r[1];                   \
                bh[2 * t2 + 1][0] = r[2]; bh[2 * t2 + 1][1] = r[3];           \
            }                                                                 \
            _Pragma("unroll")                                                 \
            for (int mf = 0; mf < 2; mf++)                                    \
                _Pragma("unroll")                                             \
                for (int nf = 0; nf < 8; nf++)                                \
                    mma_f16(acc[mf][nf], ah[mf], bh[nf]);                     \
        }                                                                     \
    }                                                                         \
    __syncthreads();

// fp32 output GEMM (output projection)
__global__ __launch_bounds__(256, 2) void gemm1_out_kernel(
    const __half* __restrict__ Ah, const __half* __restrict__ Bh,
    const float* __restrict__ bias, float* __restrict__ C, int N, int K)
{
    const int m0 = blockIdx.y * 128;
    const int n0 = blockIdx.x * 128;
    GEMM1_BODY
    const int erow = m0 + wm * 32 + (lid >> 2);
    const int ecol0 = n0 + wn * 64 + (lid & 3) * 2;
#pragma unroll
    for (int mf = 0; mf < 2; mf++) {
#pragma unroll
        for (int nf = 0; nf < 8; nf++) {
            int col = ecol0 + nf * 8;
            float2 bz = *(const float2*)(bias + col);
            float2 v0, v1;
            v0.x = acc[mf][nf][0] + bz.x; v0.y = acc[mf][nf][1] + bz.y;
            v1.x = acc[mf][nf][2] + bz.x; v1.y = acc[mf][nf][3] + bz.y;
            size_t r0 = (size_t)(erow + mf * 16) * N + col;
            *(float2*)(C + r0) = v0;
            *(float2*)(C + r0 + 8 * N) = v1;
        }
    }
}

// QKV GEMM: single product -> single fp16 plane (Q pre-scaled)
__global__ __launch_bounds__(256, 2) void gemm1_qkv_kernel(
    const __half* __restrict__ Ah, const __half* __restrict__ Bh,
    const float* __restrict__ bias,
    __half* __restrict__ qh, __half* __restrict__ kh, __half* __restrict__ vh,
    int N, int K)
{
    const int m0 = blockIdx.y * 128;
    const int n0 = blockIdx.x * 128;
    GEMM1_BODY
    const int t = n0 >> 11;                 // 0=Q 1=K 2=V
    const int head = (n0 >> 7) & (HEADS - 1);
    __half* p = (t == 0) ? qh : ((t == 1) ? kh : vh);
    const float sc = (t == 0) ? 0.08838834764831845f : 1.0f;
    const int erow = m0 + wm * 32 + (lid >> 2);
    const int lcol0 = wn * 64 + (lid & 3) * 2;
#pragma unroll
    for (int mf = 0; mf < 2; mf++) {
        int tok0 = erow + mf * 16;
        int b = tok0 >> 11;
        int s0 = tok0 & 2047;
        size_t pb = ((size_t)(b * HEADS + head) * S_LEN) * HD;
#pragma unroll
        for (int nf = 0; nf < 8; nf++) {
            int lc = lcol0 + nf * 8;
            float2 bz = *(const float2*)(bias + n0 + lc);
            float v0 = (acc[mf][nf][0] + bz.x) * sc;
            float v1 = (acc[mf][nf][1] + bz.y) * sc;
            float v2 = (acc[mf][nf][2] + bz.x) * sc;
            float v3 = (acc[mf][nf][3] + bz.y) * sc;
            *(uint32_t*)(p + pb + (size_t)s0 * HD + lc)       = packh2(v0, v1);
            *(uint32_t*)(p + pb + (size_t)(s0 + 8) * HD + lc) = packh2(v2, v3);
        }
    }
}

// ---------------------------------------------------------------------------
// Tensor-core flash attention (fp16), Q tile = 128 rows, warp-local softmax.
// 3-stage K/V cp.async pipeline, one barrier per tile, per-warp full-skip,
// mask-free fast path, Q FRAGMENTS HOISTED INTO REGISTERS.
// grid (16, HEADS, BATCH), 256 threads = 8 warps.
// ---------------------------------------------------------------------------
#define AQ_STRIDE 272                 // smem bytes per row (128 fp16 + pad)
#define SQH 0                         // 128 * 272 = 34816
#define SSTAGE0 34816
#define SSTAGE_BYTES 34816            // Kh (17408) + Vh (17408)
#define SKH 0
#define SVH 17408
#define SKID  139264                  // + stage*256 (3 stages)
#define ATTN_SMEM 140032

__global__ __launch_bounds__(256, 1) void attn_mma_kernel(
    const int* __restrict__ ids,
    __half* __restrict__ oh,
    const __half* __restrict__ qh,
    const __half* __restrict__ kh, const __half* __restrict__ vh)
{
    extern __shared__ __align__(1024) char smem[];
    const uint32_t sb = smem_to_u32(smem);
    const int tid = threadIdx.x;
    const int lane = tid & 31, wid = tid >> 5;
    const int b = blockIdx.z, h = blockIdx.y;
    const int qt = gridDim.x - 1 - blockIdx.x;       // big tiles first
    const int q0 = qt * 128;
    const size_t pbase = (size_t)(b * HEADS + h) * S_LEN * HD;
    const int* bids = ids + b * S_LEN;

    const int lr = lane >> 2;
    const int row0 = wid * 16 + lr, row1 = row0 + 8;
    const int qrow0 = q0 + row0, qrow1 = q0 + row1;
    const int qidv0 = bids[qrow0], qidv1 = bids[qrow1];
    const int qid_min = bids[q0];

    const int qwmin = q0 + wid * 16;                 // warp's first q row
    const int idq0 = bids[qwmin];
    const int idq15 = bids[qwmin + 15];
    const bool seg_uni_q = (idq0 == idq15);

    auto issue_tile = [&](int kb, int s) {
        const int k0 = kb * 64;
        const uint32_t stg = sb + SSTAGE0 + s * SSTAGE_BYTES;
#pragma unroll
        for (int j = 0; j < 4; j++) {
            int q = tid + 256 * j;
            int key = q >> 4, c16 = q & 15;
            uint32_t soff = (uint32_t)(key * AQ_STRIDE + c16 * 16);
            size_t goff = pbase + (size_t)(k0 + key) * HD + c16 * 8;
            CP_ASYNC16(stg + SKH + soff, (const char*)(kh + goff));
            CP_ASYNC16(stg + SVH + soff, (const char*)(vh + goff));
        }
        if (tid < 16)
            CP_ASYNC16(sb + SKID + s * 256 + tid * 16,
                       (const char*)(bids + k0 + tid * 4));
    };

    const int nkb = 2 * qt + 1;

    // ---- prologue: Q tile (128 rows) in group 0, tiles 0,1 in groups 0,1 ----
#pragma unroll
    for (int j = 0; j < 8; j++) {
        int q = tid + 256 * j;
        int key = q >> 4, c16 = q & 15;
        uint32_t soff = (uint32_t)(key * AQ_STRIDE + c16 * 16);
        size_t goff = pbase + (size_t)(q0 + key) * HD + c16 * 8;
        CP_ASYNC16(sb + SQH + soff, (const char*)(qh + goff));
    }
    if (bids[63] >= qid_min) issue_tile(0, 0);
    CP_COMMIT();
    if (nkb >= 1) {
        if (bids[127] >= qid_min) issue_tile(1, 1);
        CP_COMMIT();
    }

    float O[16][4];
#pragma unroll
    for (int nb = 0; nb < 16; nb++)
#pragma unroll
        for (int q = 0; q < 4; q++) O[nb][q] = 0.f;
    float m0r = -1e30f, m1r = -1e30f, l0r = 0.f, l1r = 0.f;

    const uint32_t qoffA = (uint32_t)((wid * 16 + (lane & 15)) * AQ_STRIDE + (lane >> 4) * 16);
    const uint32_t kBoff = (uint32_t)((((lane >> 1) & 8) + (lane & 7)) * AQ_STRIDE
                                      + ((lane & 8) << 1));
    const uint32_t vBoff = (uint32_t)((((lane >> 3) & 1) * 8 + (lane & 7)) * AQ_STRIDE
                                      + ((lane >> 4) & 1) * 16);

    // ---- hoist Q fragments into registers (invariant across kb loop) ----
    CP_WAIT1();          // group 0 (Q + tile 0) complete
    __syncthreads();
    uint32_t qreg[8][4];
#pragma unroll
    for (int ks = 0; ks < 8; ks++)
        ldsm4(qreg[ks], sb + SQH + qoffA + ks * 32);

    for (int kb = 0; kb <= nkb; kb++) {
        const int s = kb % 3;
        CP_WAIT1();
        __syncthreads();
        if (kb + 2 <= nkb) {
            if (bids[(kb + 2) * 64 + 63] >= qid_min) issue_tile(kb + 2, (kb + 2) % 3);
        }
        CP_COMMIT();

        const int k0 = kb * 64;
        const int kidlo = bids[k0];
        const int kidhi = bids[k0 + 63];
        // CTA-level skip (tile not even loaded) OR per-warp full-mask skip
        if (kidhi < qid_min || kidhi < idq0) continue;

        const uint32_t stg = sb + SSTAGE0 + s * SSTAGE_BYTES;

        // ---- S = Q·K^T over 64 keys (8 n-frags) ----
        float S[8][4];
#pragma unroll
        for (int nf = 0; nf < 8; nf++)
#pragma unroll
            for (int c = 0; c < 4; c++) S[nf][c] = 0.f;
#pragma unroll
        for (int ks = 0; ks < 8; ks++) {
#pragma unroll
            for (int kf = 0; kf < 4; kf++) {
                uint32_t khf[4];
                ldsm4(khf, stg + SKH + kBoff + kf * 16 * AQ_STRIDE + ks * 32);
                mma_f16(S[2 * kf],     qreg[ks], khf + 0);
                mma_f16(S[2 * kf + 1], qreg[ks], khf + 2);
            }
        }

        const bool fast = seg_uni_q && (kidlo == kidhi) && (kidlo == idq0)
                          && (k0 + 63 <= qwmin);

        float mt0 = -1e30f, mt1 = -1e30f;
        if (fast) {
#pragma unroll
            for (int nf = 0; nf < 8; nf++) {
                mt0 = fmaxf(mt0, fmaxf(S[nf][0], S[nf][1]));
                mt1 = fmaxf(mt1, fmaxf(S[nf][2], S[nf][3]));
            }
        } else {
            const uint32_t kidb = sb + SKID + s * 256;
#pragma unroll
            for (int nf = 0; nf < 8; nf++) {
                int lc = nf * 8 + 2 * (lane & 3);
                int kv0, kv1;
                asm volatile("ld.shared.v2.u32 {%0,%1}, [%2];"
                             : "=r"(kv0), "=r"(kv1) : "r"(kidb + lc * 4));
                int key = k0 + lc;
                if (key     > qrow0 || kv0 != qidv0) S[nf][0] = -1e30f;
                if (key + 1 > qrow0 || kv1 != qidv0) S[nf][1] = -1e30f;
                if (key     > qrow1 || kv0 != qidv1) S[nf][2] = -1e30f;
                if (key + 1 > qrow1 || kv1 != qidv1) S[nf][3] = -1e30f;
                mt0 = fmaxf(mt0, fmaxf(S[nf][0], S[nf][1]));
                mt1 = fmaxf(mt1, fmaxf(S[nf][2], S[nf][3]));
            }
        }
        mt0 = fmaxf(mt0, __shfl_xor_sync(0xffffffffu, mt0, 1));
        mt0 = fmaxf(mt0, __shfl_xor_sync(0xffffffffu, mt0, 2));
        mt1 = fmaxf(mt1, __shfl_xor_sync(0xffffffffu, mt1, 1));
        mt1 = fmaxf(mt1, __shfl_xor_sync(0xffffffffu, mt1, 2));

        float mn0 = fmaxf(m0r, mt0);
        float mn1 = fmaxf(m1r, mt1);
        float f0 = __expf(m0r - mn0), f1 = __expf(m1r - mn1);
        m0r = mn0; m1r = mn1;

        float rs0 = 0.f, rs1 = 0.f;
        if (fast) {
#pragma unroll
            for (int nf = 0; nf < 8; nf++) {
                float p0 = __expf(S[nf][0] - mn0);
                float p1 = __expf(S[nf][1] - mn0);
                float p2 = __expf(S[nf][2] - mn1);
                float p3 = __expf(S[nf][3] - mn1);
                S[nf][0] = p0; S[nf][1] = p1; S[nf][2] = p2; S[nf][3] = p3;
                rs0 += p0 + p1; rs1 += p2 + p3;
            }
        } else {
#pragma unroll
            for (int nf = 0; nf < 8; nf++) {
                float p0 = (S[nf][0] < -1e29f) ? 0.f : __expf(S[nf][0] - mn0);
                float p1 = (S[nf][1] < -1e29f) ? 0.f : __expf(S[nf][1] - mn0);
                float p2 = (S[nf][2] < -1e29f) ? 0.f : __expf(S[nf][2] - mn1);
                float p3 = (S[nf][3] < -1e29f) ? 0.f : __expf(S[nf][3] - mn1);
                S[nf][0] = p0; S[nf][1] = p1; S[nf][2] = p2; S[nf][3] = p3;
                rs0 += p0 + p1; rs1 += p2 + p3;
            }
        }
        rs0 += __shfl_xor_sync(0xffffffffu, rs0, 1);
        rs0 += __shfl_xor_sync(0xffffffffu, rs0, 2);
        rs1 += __shfl_xor_sync(0xffffffffu, rs1, 1);
        rs1 += __shfl_xor_sync(0xffffffffu, rs1, 2);
        l0r = l0r * f0 + rs0;
        l1r = l1r * f1 + rs1;

        // rescale O
#pragma unroll
        for (int nb = 0; nb < 16; nb++) {
            O[nb][0] *= f0; O[nb][1] *= f0;
            O[nb][2] *= f1; O[nb][3] *= f1;
        }

        // ---- O += RN16(P)·V over the 64-key dim (4 k16 chunks) ----
#pragma unroll
        for (int ks2 = 0; ks2 < 4; ks2++) {
            uint32_t ah[4];
            ah[0] = packh2(S[2 * ks2][0],     S[2 * ks2][1]);
            ah[1] = packh2(S[2 * ks2][2],     S[2 * ks2][3]);
            ah[2] = packh2(S[2 * ks2 + 1][0], S[2 * ks2 + 1][1]);
            ah[3] = packh2(S[2 * ks2 + 1][2], S[2 * ks2 + 1][3]);
            uint32_t ro = vBoff + ks2 * 16 * AQ_STRIDE;
#pragma unroll
            for (int np = 0; np < 4; np++) {
                uint32_t vh0[4], vh1[4];
                ldsm4t(vh0, stg + SVH + ro + (2 * np) * 32);
                ldsm4t(vh1, stg + SVH + ro + (2 * np + 1) * 32);
                int o0 = 4 * np;
                mma_f16(O[o0 + 0], ah, vh0 + 0); mma_f16(O[o0 + 1], ah, vh0 + 2);
                mma_f16(O[o0 + 2], ah, vh1 + 0); mma_f16(O[o0 + 3], ah, vh1 + 2);
            }
        }
    }

    // ---- epilogue: warp-local normalize, write fp16 plane directly ----
    float inv0 = 1.f / l0r;
    float inv1 = 1.f / l1r;
    const size_t g0 = ((size_t)b * S_LEN + qrow0) * DIM + h * HD;
    const size_t g1 = ((size_t)b * S_LEN + qrow1) * DIM + h * HD;
#pragma unroll
    for (int nb = 0; nb < 16; nb++) {
        int col = nb * 8 + 2 * (lane & 3);
        *(uint32_t*)(oh + g0 + col) = packh2(O[nb][0] * inv0, O[nb][1] * inv0);
        *(uint32_t*)(oh + g1 + col) = packh2(O[nb][2] * inv1, O[nb][3] * inv1);
    }
}

// ---------------------------------------------------------------------------
extern "C" void kernel_launch(void* const* d_in, const int* in_sizes, int n_in,
                              void* d_out, int out_size)
{
    const float* x    = (const float*)d_in[0];   // [4,2048,2048]
    const int*   ids  = (const int*)d_in[1];     // [4,2048]
    const float* Wqkv = (const float*)d_in[2];   // [2048,6144]
    const float* bqkv = (const float*)d_in[3];   // [6144]
    const float* Wo   = (const float*)d_in[4];   // [2048,2048]
    const float* bo   = (const float*)d_in[5];   // [2048]
    float* out = (float*)d_out;

    __half *qh, *kh, *vh, *xh, *ah, *wqh, *woh;
    cudaGetSymbolAddress((void**)&qh, g_qh);
    cudaGetSymbolAddress((void**)&kh, g_kh);
    cudaGetSymbolAddress((void**)&vh, g_vh);
    cudaGetSymbolAddress((void**)&xh, g_xh);
    cudaGetSymbolAddress((void**)&ah, g_ah);
    cudaGetSymbolAddress((void**)&wqh, g_wqh);
    cudaGetSymbolAddress((void**)&woh, g_woh);

    cudaFuncSetAttribute(gemm1_out_kernel,
                         cudaFuncAttributeMaxDynamicSharedMemorySize, GSMEM_BYTES);
    cudaFuncSetAttribute(gemm1_qkv_kernel,
                         cudaFuncAttributeMaxDynamicSharedMemorySize, GSMEM_BYTES);
    cudaFuncSetAttribute(attn_mma_kernel,
                         cudaFuncAttributeMaxDynamicSharedMemorySize, ATTN_SMEM);

    const int M = BATCH * S_LEN;   // 8192

    // 0) round x, round+transpose weights (one-shot)
    round_kernel<<<1184, 256>>>(x, xh, (size_t)M * DIM / 2);
    {
        dim3 blk(32, 8);
        transpose_round_kernel<<<dim3(3 * DIM / 32, DIM / 32), blk>>>(Wqkv, wqh, DIM, 3 * DIM);
        transpose_round_kernel<<<dim3(DIM / 32, DIM / 32), blk>>>(Wo, woh, DIM, DIM);
    }
    // 1) QKV = x @ Wqkv + bqkv -> fp16 planes (Q pre-scaled), single product
    {
        dim3 grid(3 * DIM / 128, M / 128);
        gemm1_qkv_kernel<<<grid, 256, GSMEM_BYTES>>>(
            xh, wqh, bqkv, qh, kh, vh, 3 * DIM, DIM);
    }
    // 2) flash attention -> single fp16 plane (Q tile 128)
    {
        dim3 grid(S_LEN / 128, HEADS, BATCH);
        attn_mma_kernel<<<grid, 256, ATTN_SMEM>>>(ids, ah, qh, kh, vh);
    }
    // 3) out = attn @ Wo + bo  [8192, 2048] fp32, single product
    {
        dim3 grid(DIM / 128, M / 128);
        gemm1_out_kernel<<<grid, 256, GSMEM_BYTES>>>(ah, woh, bo, out, DIM, DIM);
    }
}

// round 16
// speedup vs baseline: 1.0364x; 1.0084x over previous
#include <cuda_runtime.h>
#include <cuda_fp16.h>
#include <cstdint>
#include <cstddef>

#define S_LEN 2048
#define DIM   2048
#define HEADS 16
#define HD    128
#define BATCH 4

// Scratch (allocation-free rule: __device__ globals)
#define PLANE_ELEMS ((size_t)BATCH * HEADS * S_LEN * HD)
__device__ __half g_qh[PLANE_ELEMS];
__device__ __half g_kh[PLANE_ELEMS];
__device__ __half g_vh[PLANE_ELEMS];
__device__ __half g_xh[(size_t)BATCH * S_LEN * DIM];
__device__ __half g_ah[(size_t)BATCH * S_LEN * DIM];
__device__ __half g_wqh[(size_t)(3 * DIM) * DIM];
__device__ __half g_woh[(size_t)DIM * DIM];

// ---------------------------------------------------------------------------
// helpers
// ---------------------------------------------------------------------------
__device__ __forceinline__ uint32_t smem_to_u32(const void* p) {
    uint32_t a;
    asm("{ .reg .u64 t; cvta.to.shared.u64 t, %1; cvt.u32.u64 %0, t; }"
        : "=r"(a) : "l"(p));
    return a;
}

__device__ __forceinline__ void ldsm4(uint32_t* r, uint32_t addr) {
    asm volatile("ldmatrix.sync.aligned.m8n8.x4.shared.b16 {%0,%1,%2,%3}, [%4];"
                 : "=r"(r[0]), "=r"(r[1]), "=r"(r[2]), "=r"(r[3]) : "r"(addr));
}

__device__ __forceinline__ void ldsm4t(uint32_t* r, uint32_t addr) {
    asm volatile("ldmatrix.sync.aligned.m8n8.x4.trans.shared.b16 {%0,%1,%2,%3}, [%4];"
                 : "=r"(r[0]), "=r"(r[1]), "=r"(r[2]), "=r"(r[3]) : "r"(addr));
}

__device__ __forceinline__ void mma_f16(float* d, const uint32_t* a, const uint32_t* b) {
    asm volatile(
        "mma.sync.aligned.m16n8k16.row.col.f32.f16.f16.f32 "
        "{%0,%1,%2,%3}, {%4,%5,%6,%7}, {%8,%9}, {%0,%1,%2,%3};"
        : "+f"(d[0]), "+f"(d[1]), "+f"(d[2]), "+f"(d[3])
        : "r"(a[0]), "r"(a[1]), "r"(a[2]), "r"(a[3]), "r"(b[0]), "r"(b[1]));
}

// pack (x0,x1) -> fp16x2 (low half = x0)
__device__ __forceinline__ uint32_t packh2(float x0, float x1) {
    __half2 h = __floats2half2_rn(x0, x1);
    return *(uint32_t*)&h;
}

#define CP_ASYNC16(dst, src) \
    asm volatile("cp.async.cg.shared.global [%0], [%1], 16;" \
                 :: "r"(dst), "l"(src) : "memory")
#define CP_COMMIT() asm volatile("cp.async.commit_group;" ::: "memory")
#define CP_WAIT1()  asm volatile("cp.async.wait_group 1;" ::: "memory")

// ---------------------------------------------------------------------------
// Elementwise round: fp32 -> fp16 plane
// ---------------------------------------------------------------------------
__global__ __launch_bounds__(256) void round_kernel(
    const float* __restrict__ in, __half* __restrict__ out, size_t n2)
{
    size_t i = (size_t)blockIdx.x * blockDim.x + threadIdx.x;
    size_t stride = (size_t)gridDim.x * blockDim.x;
    for (; i < n2; i += stride) {
        float2 v = *(const float2*)(in + 2 * i);
        *(uint32_t*)(out + 2 * i) = packh2(v.x, v.y);
    }
}

// ---------------------------------------------------------------------------
// Transpose + round: fp32 in[R][C] -> fp16 out[C][R]
// ---------------------------------------------------------------------------
__global__ __launch_bounds__(256) void transpose_round_kernel(
    const float* __restrict__ in, __half* __restrict__ out, int R, int C)
{
    __shared__ float t[32][33];
    int bx = blockIdx.x * 32;
    int by = blockIdx.y * 32;
    int x = threadIdx.x, y = threadIdx.y;   // 32 x 8
#pragma unroll
    for (int j = 0; j < 32; j += 8)
        t[y + j][x] = in[(size_t)(by + y + j) * C + bx + x];
    __syncthreads();
#pragma unroll
    for (int jj = 0; jj < 2; jj++) {
        int cp = y + 8 * jj;                 // 0..15 col pair index
        uint32_t h = packh2(t[cp * 2][x], t[cp * 2 + 1][x]);
        size_t o = (size_t)(bx + x) * R + by + cp * 2;
        *(uint32_t*)(out + o) = h;
    }
}

// ---------------------------------------------------------------------------
// fp16 single-product GEMM (measured-best config): C = Ah @ Bh^T (+bias).
// 128x128 tile, BK=64, 256 threads = 8 warps (4x2), warp tile 32x64.
// 3-stage cp.async pipeline, 2 CTAs/SM.
// ---------------------------------------------------------------------------
#define GSTRIDE      144
#define GB_OFF       18432
#define GSTAGE_BYTES 36864
#define GSMEM_BYTES  (3 * GSTAGE_BYTES)

#define GEMM1_BODY                                                            \
    extern __shared__ __align__(1024) char smem[];                            \
    const uint32_t sb = smem_to_u32(smem);                                    \
    const int tid = threadIdx.x;                                              \
    const int wid = tid >> 5, lid = tid & 31;                                 \
    const int wm = wid >> 1;                                                  \
    const int wn = wid & 1;                                                   \
    const uint32_t aBase = (uint32_t)((wm * 32 + (lid & 15)) * GSTRIDE + (lid >> 4) * 16); \
    const uint32_t bBase = (uint32_t)((wn * 64 + ((lid >> 1) & 8) + (lid & 7)) * GSTRIDE \
                                      + ((lid & 8) << 1));                    \
    float acc[2][8][4];                                                       \
    _Pragma("unroll")                                                         \
    for (int mf = 0; mf < 2; mf++)                                            \
        _Pragma("unroll")                                                     \
        for (int nf = 0; nf < 8; nf++)                                        \
            _Pragma("unroll")                                                 \
            for (int q = 0; q < 4; q++) acc[mf][nf][q] = 0.f;                 \
    const int niter = K >> 6;                                                 \
    auto issue = [&](int i, int s) {                                          \
        const int k0 = i << 6;                                                \
        const uint32_t base = sb + s * GSTAGE_BYTES;                          \
        _Pragma("unroll")                                                     \
        for (int j = 0; j < 4; j++) {                                         \
            int c = tid + 256 * j;                                            \
            int row = c >> 3, c8 = c & 7;                                     \
            uint32_t so = (uint32_t)(row * GSTRIDE + c8 * 16);                \
            CP_ASYNC16(base + so,          (const char*)(Ah + (size_t)(m0 + row) * K + k0 + c8 * 8)); \
            CP_ASYNC16(base + GB_OFF + so, (const char*)(Bh + (size_t)(n0 + row) * K + k0 + c8 * 8)); \
        }                                                                     \
    };                                                                        \
    issue(0, 0); CP_COMMIT();                                                 \
    if (niter > 1) { issue(1, 1); CP_COMMIT(); }                              \
    for (int i = 0; i < niter; i++) {                                         \
        const int s = i % 3;                                                  \
        CP_WAIT1();                                                           \
        __syncthreads();                                                      \
        if (i + 2 < niter) issue(i + 2, (i + 2) % 3);                         \
        CP_COMMIT();                                                          \
        const uint32_t sA = sb + s * GSTAGE_BYTES;                            \
        _Pragma("unroll")                                                     \
        for (int kstep = 0; kstep < 4; kstep++) {                             \
            const uint32_t koff = kstep * 32;                                 \
            uint32_t ah[2][4];                                                \
            ldsm4(ah[0], sA + aBase + koff);                                  \
            ldsm4(ah[1], sA + aBase + 16 * GSTRIDE + koff);                   \
            uint32_t bh[8][2];                                                \
            _Pragma("unroll")                                                 \
            for (int t2 = 0; t2 < 4; t2++) {                                  \
                uint32_t r[4];                                                \
                ldsm4(r, sA + GB_OFF + bBase + t2 * 16 * GSTRIDE + koff);     \
                bh[2 * t2][0] = r[0]; bh[2 * t2][1] = r[1];                   \
                bh[2 * t2 + 1][0] = r[2]; bh[2 * t2 + 1][1] = r[3];           \
            }                                                                 \
            _Pragma("unroll")                                                 \
            for (int mf = 0; mf < 2; mf++)                                    \
                _Pragma("unroll")                                             \
                for (int nf = 0; nf < 8; nf++)                                \
                    mma_f16(acc[mf][nf], ah[mf], bh[nf]);                     \
        }                                                                     \
    }                                                                         \
    __syncthreads();

// fp32 output GEMM (output projection)
__global__ __launch_bounds__(256, 2) void gemm1_out_kernel(
    const __half* __restrict__ Ah, const __half* __restrict__ Bh,
    const float* __restrict__ bias, float* __restrict__ C, int N, int K)
{
    const int m0 = blockIdx.y * 128;
    const int n0 = blockIdx.x * 128;
    GEMM1_BODY
    const int erow = m0 + wm * 32 + (lid >> 2);
    const int ecol0 = n0 + wn * 64 + (lid & 3) * 2;
#pragma unroll
    for (int mf = 0; mf < 2; mf++) {
#pragma unroll
        for (int nf = 0; nf < 8; nf++) {
            int col = ecol0 + nf * 8;
            float2 bz = *(const float2*)(bias + col);
            float2 v0, v1;
            v0.x = acc[mf][nf][0] + bz.x; v0.y = acc[mf][nf][1] + bz.y;
            v1.x = acc[mf][nf][2] + bz.x; v1.y = acc[mf][nf][3] + bz.y;
            size_t r0 = (size_t)(erow + mf * 16) * N + col;
            *(float2*)(C + r0) = v0;
            *(float2*)(C + r0 + 8 * N) = v1;
        }
    }
}

// QKV GEMM: single product -> single fp16 plane (Q pre-scaled)
__global__ __launch_bounds__(256, 2) void gemm1_qkv_kernel(
    const __half* __restrict__ Ah, const __half* __restrict__ Bh,
    const float* __restrict__ bias,
    __half* __restrict__ qh, __half* __restrict__ kh, __half* __restrict__ vh,
    int N, int K)
{
    const int m0 = blockIdx.y * 128;
    const int n0 = blockIdx.x * 128;
    GEMM1_BODY
    const int t = n0 >> 11;                 // 0=Q 1=K 2=V
    const int head = (n0 >> 7) & (HEADS - 1);
    __half* p = (t == 0) ? qh : ((t == 1) ? kh : vh);
    const float sc = (t == 0) ? 0.08838834764831845f : 1.0f;
    const int erow = m0 + wm * 32 + (lid >> 2);
    const int lcol0 = wn * 64 + (lid & 3) * 2;
#pragma unroll
    for (int mf = 0; mf < 2; mf++) {
        int tok0 = erow + mf * 16;
        int b = tok0 >> 11;
        int s0 = tok0 & 2047;
        size_t pb = ((size_t)(b * HEADS + head) * S_LEN) * HD;
#pragma unroll
        for (int nf = 0; nf < 8; nf++) {
            int lc = lcol0 + nf * 8;
            float2 bz = *(const float2*)(bias + n0 + lc);
            float v0 = (acc[mf][nf][0] + bz.x) * sc;
            float v1 = (acc[mf][nf][1] + bz.y) * sc;
            float v2 = (acc[mf][nf][2] + bz.x) * sc;
            float v3 = (acc[mf][nf][3] + bz.y) * sc;
            *(uint32_t*)(p + pb + (size_t)s0 * HD + lc)       = packh2(v0, v1);
            *(uint32_t*)(p + pb + (size_t)(s0 + 8) * HD + lc) = packh2(v2, v3);
        }
    }
}

// ---------------------------------------------------------------------------
// Tensor-core flash attention (fp16), Q tile = 128 rows, warp-local softmax.
// 2-stage K/V cp.async pipeline, 2 barriers/tile, 2 CTAs/SM.
// Per-warp full-skip and mask-free fast path.
// grid (16, HEADS, BATCH), 256 threads = 8 warps.
// ---------------------------------------------------------------------------
#define AQ_STRIDE 272                 // smem bytes per row (128 fp16 + pad)
#define SQH 0                         // 128 * 272 = 34816
#define SSTAGE0 34816
#define SSTAGE_BYTES 34816            // Kh (17408) + Vh (17408)
#define SKH 0
#define SVH 17408
#define SKID  104448                  // + stage*256 (2 stages)
#define ATTN_SMEM 105472

__global__ __launch_bounds__(256, 2) void attn_mma_kernel(
    const int* __restrict__ ids,
    __half* __restrict__ oh,
    const __half* __restrict__ qh,
    const __half* __restrict__ kh, const __half* __restrict__ vh)
{
    extern __shared__ __align__(1024) char smem[];
    const uint32_t sb = smem_to_u32(smem);
    const int tid = threadIdx.x;
    const int lane = tid & 31, wid = tid >> 5;
    const int b = blockIdx.z, h = blockIdx.y;
    const int qt = gridDim.x - 1 - blockIdx.x;       // big tiles first
    const int q0 = qt * 128;
    const size_t pbase = (size_t)(b * HEADS + h) * S_LEN * HD;
    const int* bids = ids + b * S_LEN;

    const int lr = lane >> 2;
    const int row0 = wid * 16 + lr, row1 = row0 + 8;
    const int qrow0 = q0 + row0, qrow1 = q0 + row1;
    const int qidv0 = bids[qrow0], qidv1 = bids[qrow1];
    const int qid_min = bids[q0];

    const int qwmin = q0 + wid * 16;                 // warp's first q row
    const int idq0 = bids[qwmin];
    const int idq15 = bids[qwmin + 15];
    const bool seg_uni_q = (idq0 == idq15);

    auto issue_tile = [&](int kb, int s) {
        const int k0 = kb * 64;
        const uint32_t stg = sb + SSTAGE0 + s * SSTAGE_BYTES;
#pragma unroll
        for (int j = 0; j < 4; j++) {
            int q = tid + 256 * j;
            int key = q >> 4, c16 = q & 15;
            uint32_t soff = (uint32_t)(key * AQ_STRIDE + c16 * 16);
            size_t goff = pbase + (size_t)(k0 + key) * HD + c16 * 8;
            CP_ASYNC16(stg + SKH + soff, (const char*)(kh + goff));
            CP_ASYNC16(stg + SVH + soff, (const char*)(vh + goff));
        }
        if (tid < 16)
            CP_ASYNC16(sb + SKID + s * 256 + tid * 16,
                       (const char*)(bids + k0 + tid * 4));
    };

    const int nkb = 2 * qt + 1;

    // ---- prologue: Q tile (128 rows) + tile 0 in group 0, tile 1 in group 1
#pragma unroll
    for (int j = 0; j < 8; j++) {
        int q = tid + 256 * j;
        int key = q >> 4, c16 = q & 15;
        uint32_t soff = (uint32_t)(key * AQ_STRIDE + c16 * 16);
        size_t goff = pbase + (size_t)(q0 + key) * HD + c16 * 8;
        CP_ASYNC16(sb + SQH + soff, (const char*)(qh + goff));
    }
    if (bids[63] >= qid_min) issue_tile(0, 0);
    CP_COMMIT();
    if (bids[127] >= qid_min) issue_tile(1, 1);
    CP_COMMIT();

    float O[16][4];
#pragma unroll
    for (int nb = 0; nb < 16; nb++)
#pragma unroll
        for (int q = 0; q < 4; q++) O[nb][q] = 0.f;
    float m0r = -1e30f, m1r = -1e30f, l0r = 0.f, l1r = 0.f;

    const uint32_t qoffA = (uint32_t)((wid * 16 + (lane & 15)) * AQ_STRIDE + (lane >> 4) * 16);
    const uint32_t kBoff = (uint32_t)((((lane >> 1) & 8) + (lane & 7)) * AQ_STRIDE
                                      + ((lane & 8) << 1));
    const uint32_t vBoff = (uint32_t)((((lane >> 3) & 1) * 8 + (lane & 7)) * AQ_STRIDE
                                      + ((lane >> 4) & 1) * 16);

    for (int kb = 0; kb <= nkb; kb++) {
        const int s = kb & 1;
        CP_WAIT1();
        __syncthreads();

        const int k0 = kb * 64;
        const int kidlo = bids[k0];
        const int kidhi = bids[k0 + 63];
        const bool skip = (kidhi < qid_min) || (kidhi < idq0);

        if (!skip) {
            const uint32_t stg = sb + SSTAGE0 + s * SSTAGE_BYTES;

            // ---- S = Q·K^T over 64 keys (8 n-frags) ----
            float S[8][4];
#pragma unroll
            for (int nf = 0; nf < 8; nf++)
#pragma unroll
                for (int c = 0; c < 4; c++) S[nf][c] = 0.f;
#pragma unroll
            for (int ks = 0; ks < 8; ks++) {
                uint32_t ah[4];
                ldsm4(ah, sb + SQH + qoffA + ks * 32);
#pragma unroll
                for (int kf = 0; kf < 4; kf++) {
                    uint32_t khf[4];
                    ldsm4(khf, stg + SKH + kBoff + kf * 16 * AQ_STRIDE + ks * 32);
                    mma_f16(S[2 * kf],     ah, khf + 0);
                    mma_f16(S[2 * kf + 1], ah, khf + 2);
                }
            }

            const bool fast = seg_uni_q && (kidlo == kidhi) && (kidlo == idq0)
                              && (k0 + 63 <= qwmin);

            float mt0 = -1e30f, mt1 = -1e30f;
            if (fast) {
#pragma unroll
                for (int nf = 0; nf < 8; nf++) {
                    mt0 = fmaxf(mt0, fmaxf(S[nf][0], S[nf][1]));
                    mt1 = fmaxf(mt1, fmaxf(S[nf][2], S[nf][3]));
                }
            } else {
                const uint32_t kidb = sb + SKID + s * 256;
#pragma unroll
                for (int nf = 0; nf < 8; nf++) {
                    int lc = nf * 8 + 2 * (lane & 3);
                    int kv0, kv1;
                    asm volatile("ld.shared.v2.u32 {%0,%1}, [%2];"
                                 : "=r"(kv0), "=r"(kv1) : "r"(kidb + lc * 4));
                    int key = k0 + lc;
                    if (key     > qrow0 || kv0 != qidv0) S[nf][0] = -1e30f;
                    if (key + 1 > qrow0 || kv1 != qidv0) S[nf][1] = -1e30f;
                    if (key     > qrow1 || kv0 != qidv1) S[nf][2] = -1e30f;
                    if (key + 1 > qrow1 || kv1 != qidv1) S[nf][3] = -1e30f;
                    mt0 = fmaxf(mt0, fmaxf(S[nf][0], S[nf][1]));
                    mt1 = fmaxf(mt1, fmaxf(S[nf][2], S[nf][3]));
                }
            }
            mt0 = fmaxf(mt0, __shfl_xor_sync(0xffffffffu, mt0, 1));
            mt0 = fmaxf(mt0, __shfl_xor_sync(0xffffffffu, mt0, 2));
            mt1 = fmaxf(mt1, __shfl_xor_sync(0xffffffffu, mt1, 1));
            mt1 = fmaxf(mt1, __shfl_xor_sync(0xffffffffu, mt1, 2));

            float mn0 = fmaxf(m0r, mt0);
            float mn1 = fmaxf(m1r, mt1);
            float f0 = __expf(m0r - mn0), f1 = __expf(m1r - mn1);
            m0r = mn0; m1r = mn1;

            float rs0 = 0.f, rs1 = 0.f;
            if (fast) {
#pragma unroll
                for (int nf = 0; nf < 8; nf++) {
                    float p0 = __expf(S[nf][0] - mn0);
                    float p1 = __expf(S[nf][1] - mn0);
                    float p2 = __expf(S[nf][2] - mn1);
                    float p3 = __expf(S[nf][3] - mn1);
                    S[nf][0] = p0; S[nf][1] = p1; S[nf][2] = p2; S[nf][3] = p3;
                    rs0 += p0 + p1; rs1 += p2 + p3;
                }
            } else {
#pragma unroll
                for (int nf = 0; nf < 8; nf++) {
                    float p0 = (S[nf][0] < -1e29f) ? 0.f : __expf(S[nf][0] - mn0);
                    float p1 = (S[nf][1] < -1e29f) ? 0.f : __expf(S[nf][1] - mn0);
                    float p2 = (S[nf][2] < -1e29f) ? 0.f : __expf(S[nf][2] - mn1);
                    float p3 = (S[nf][3] < -1e29f) ? 0.f : __expf(S[nf][3] - mn1);
                    S[nf][0] = p0; S[nf][1] = p1; S[nf][2] = p2; S[nf][3] = p3;
                    rs0 += p0 + p1; rs1 += p2 + p3;
                }
            }
            rs0 += __shfl_xor_sync(0xffffffffu, rs0, 1);
            rs0 += __shfl_xor_sync(0xffffffffu, rs0, 2);
            rs1 += __shfl_xor_sync(0xffffffffu, rs1, 1);
            rs1 += __shfl_xor_sync(0xffffffffu, rs1, 2);
            l0r = l0r * f0 + rs0;
            l1r = l1r * f1 + rs1;

            // rescale O
#pragma unroll
            for (int nb = 0; nb < 16; nb++) {
                O[nb][0] *= f0; O[nb][1] *= f0;
                O[nb][2] *= f1; O[nb][3] *= f1;
            }

            // ---- O += RN16(P)·V over the 64-key dim (4 k16 chunks) ----
#pragma unroll
            for (int ks2 = 0; ks2 < 4; ks2++) {
                uint32_t ah[4];
                ah[0] = packh2(S[2 * ks2][0],     S[2 * ks2][1]);
                ah[1] = packh2(S[2 * ks2][2],     S[2 * ks2][3]);
                ah[2] = packh2(S[2 * ks2 + 1][0], S[2 * ks2 + 1][1]);
                ah[3] = packh2(S[2 * ks2 + 1][2], S[2 * ks2 + 1][3]);
                uint32_t ro = vBoff + ks2 * 16 * AQ_STRIDE;
#pragma unroll
                for (int np = 0; np < 4; np++) {
                    uint32_t vh0[4], vh1[4];
                    ldsm4t(vh0, stg + SVH + ro + (2 * np) * 32);
                    ldsm4t(vh1, stg + SVH + ro + (2 * np + 1) * 32);
                    int o0 = 4 * np;
                    mma_f16(O[o0 + 0], ah, vh0 + 0); mma_f16(O[o0 + 1], ah, vh0 + 2);
                    mma_f16(O[o0 + 2], ah, vh1 + 0); mma_f16(O[o0 + 3], ah, vh1 + 2);
                }
            }
        }

        // stage s is free only after every warp finished reading it
        __syncthreads();
        if (kb + 2 <= nkb) {
            if (bids[(kb + 2) * 64 + 63] >= qid_min) issue_tile(kb + 2, s);
        }
        CP_COMMIT();
    }

    // ---- epilogue: warp-local normalize, write fp16 plane directly ----
    float inv0 = 1.f / l0r;
    float inv1 = 1.f / l1r;
    const size_t g0 = ((size_t)b * S_LEN + qrow0) * DIM + h * HD;
    const size_t g1 = ((size_t)b * S_LEN + qrow1) * DIM + h * HD;
#pragma unroll
    for (int nb = 0; nb < 16; nb++) {
        int col = nb * 8 + 2 * (lane & 3);
        *(uint32_t*)(oh + g0 + col) = packh2(O[nb][0] * inv0, O[nb][1] * inv0);
        *(uint32_t*)(oh + g1 + col) = packh2(O[nb][2] * inv1, O[nb][3] * inv1);
    }
}

// ---------------------------------------------------------------------------
extern "C" void kernel_launch(void* const* d_in, const int* in_sizes, int n_in,
                              void* d_out, int out_size)
{
    const float* x    = (const float*)d_in[0];   // [4,2048,2048]
    const int*   ids  = (const int*)d_in[1];     // [4,2048]
    const float* Wqkv = (const float*)d_in[2];   // [2048,6144]
    const float* bqkv = (const float*)d_in[3];   // [6144]
    const float* Wo   = (const float*)d_in[4];   // [2048,2048]
    const float* bo   = (const float*)d_in[5];   // [2048]
    float* out = (float*)d_out;

    __half *qh, *kh, *vh, *xh, *ah, *wqh, *woh;
    cudaGetSymbolAddress((void**)&qh, g_qh);
    cudaGetSymbolAddress((void**)&kh, g_kh);
    cudaGetSymbolAddress((void**)&vh, g_vh);
    cudaGetSymbolAddress((void**)&xh, g_xh);
    cudaGetSymbolAddress((void**)&ah, g_ah);
    cudaGetSymbolAddress((void**)&wqh, g_wqh);
    cudaGetSymbolAddress((void**)&woh, g_woh);

    cudaFuncSetAttribute(gemm1_out_kernel,
                         cudaFuncAttributeMaxDynamicSharedMemorySize, GSMEM_BYTES);
    cudaFuncSetAttribute(gemm1_qkv_kernel,
                         cudaFuncAttributeMaxDynamicSharedMemorySize, GSMEM_BYTES);
    cudaFuncSetAttribute(attn_mma_kernel,
                         cudaFuncAttributeMaxDynamicSharedMemorySize, ATTN_SMEM);

    const int M = BATCH * S_LEN;   // 8192

    // 0) round x, round+transpose weights (one-shot)
    round_kernel<<<1184, 256>>>(x, xh, (size_t)M * DIM / 2);
    {
        dim3 blk(32, 8);
        transpose_round_kernel<<<dim3(3 * DIM / 32, DIM / 32), blk>>>(Wqkv, wqh, DIM, 3 * DIM);
        transpose_round_kernel<<<dim3(DIM / 32, DIM / 32), blk>>>(Wo, woh, DIM, DIM);
    }
    // 1) QKV = x @ Wqkv + bqkv -> fp16 planes (Q pre-scaled), single product
    {
        dim3 grid(3 * DIM / 128, M / 128);
        gemm1_qkv_kernel<<<grid, 256, GSMEM_BYTES>>>(
            xh, wqh, bqkv, qh, kh, vh, 3 * DIM, DIM);
    }
    // 2) flash attention -> single fp16 plane (Q tile 128, 2 CTAs/SM)
    {
        dim3 grid(S_LEN / 128, HEADS, BATCH);
        attn_mma_kernel<<<grid, 256, ATTN_SMEM>>>(ids, ah, qh, kh, vh);
    }
    // 3) out = attn @ Wo + bo  [8192, 2048] fp32, single product
    {
        dim3 grid(DIM / 128, M / 128);
        gemm1_out_kernel<<<grid, 256, GSMEM_BYTES>>>(ah, woh, bo, out, DIM, DIM);
    }
}

// round 17
// speedup vs baseline: 1.0474x; 1.0106x over previous
#include <cuda_runtime.h>
#include <cuda_fp16.h>
#include <cstdint>
#include <cstddef>

#define S_LEN 2048
#define DIM   2048
#define HEADS 16
#define HD    128
#define BATCH 4

// Scratch (allocation-free rule: __device__ globals)
#define PLANE_ELEMS ((size_t)BATCH * HEADS * S_LEN * HD)
__device__ __half g_qh[PLANE_ELEMS];
__device__ __half g_kh[PLANE_ELEMS];
__device__ __half g_vh[PLANE_ELEMS];
__device__ __half g_xh[(size_t)BATCH * S_LEN * DIM];
__device__ __half g_ah[(size_t)BATCH * S_LEN * DIM];
__device__ __half g_wqh[(size_t)(3 * DIM) * DIM];
__device__ __half g_woh[(size_t)DIM * DIM];

// ---------------------------------------------------------------------------
// helpers
// ---------------------------------------------------------------------------
__device__ __forceinline__ uint32_t smem_to_u32(const void* p) {
    uint32_t a;
    asm("{ .reg .u64 t; cvta.to.shared.u64 t, %1; cvt.u32.u64 %0, t; }"
        : "=r"(a) : "l"(p));
    return a;
}

__device__ __forceinline__ void ldsm4(uint32_t* r, uint32_t addr) {
    asm volatile("ldmatrix.sync.aligned.m8n8.x4.shared.b16 {%0,%1,%2,%3}, [%4];"
                 : "=r"(r[0]), "=r"(r[1]), "=r"(r[2]), "=r"(r[3]) : "r"(addr));
}

__device__ __forceinline__ void ldsm4t(uint32_t* r, uint32_t addr) {
    asm volatile("ldmatrix.sync.aligned.m8n8.x4.trans.shared.b16 {%0,%1,%2,%3}, [%4];"
                 : "=r"(r[0]), "=r"(r[1]), "=r"(r[2]), "=r"(r[3]) : "r"(addr));
}

__device__ __forceinline__ void mma_f16(float* d, const uint32_t* a, const uint32_t* b) {
    asm volatile(
        "mma.sync.aligned.m16n8k16.row.col.f32.f16.f16.f32 "
        "{%0,%1,%2,%3}, {%4,%5,%6,%7}, {%8,%9}, {%0,%1,%2,%3};"
        : "+f"(d[0]), "+f"(d[1]), "+f"(d[2]), "+f"(d[3])
        : "r"(a[0]), "r"(a[1]), "r"(a[2]), "r"(a[3]), "r"(b[0]), "r"(b[1]));
}

// pack (x0,x1) -> fp16x2 (low half = x0)
__device__ __forceinline__ uint32_t packh2(float x0, float x1) {
    __half2 h = __floats2half2_rn(x0, x1);
    return *(uint32_t*)&h;
}

#define CP_ASYNC16(dst, src) \
    asm volatile("cp.async.cg.shared.global [%0], [%1], 16;" \
                 :: "r"(dst), "l"(src) : "memory")
#define CP_COMMIT() asm volatile("cp.async.commit_group;" ::: "memory")
#define CP_WAIT1()  asm volatile("cp.async.wait_group 1;" ::: "memory")

// ---------------------------------------------------------------------------
// Elementwise round: fp32 -> fp16 plane
// ---------------------------------------------------------------------------
__global__ __launch_bounds__(256) void round_kernel(
    const float* __restrict__ in, __half* __restrict__ out, size_t n2)
{
    size_t i = (size_t)blockIdx.x * blockDim.x + threadIdx.x;
    size_t stride = (size_t)gridDim.x * blockDim.x;
    for (; i < n2; i += stride) {
        float2 v = *(const float2*)(in + 2 * i);
        *(uint32_t*)(out + 2 * i) = packh2(v.x, v.y);
    }
}

// ---------------------------------------------------------------------------
// Transpose + round: fp32 in[R][C] -> fp16 out[C][R]
// ---------------------------------------------------------------------------
__global__ __launch_bounds__(256) void transpose_round_kernel(
    const float* __restrict__ in, __half* __restrict__ out, int R, int C)
{
    __shared__ float t[32][33];
    int bx = blockIdx.x * 32;
    int by = blockIdx.y * 32;
    int x = threadIdx.x, y = threadIdx.y;   // 32 x 8
#pragma unroll
    for (int j = 0; j < 32; j += 8)
        t[y + j][x] = in[(size_t)(by + y + j) * C + bx + x];
    __syncthreads();
#pragma unroll
    for (int jj = 0; jj < 2; jj++) {
        int cp = y + 8 * jj;                 // 0..15 col pair index
        uint32_t h = packh2(t[cp * 2][x], t[cp * 2 + 1][x]);
        size_t o = (size_t)(bx + x) * R + by + cp * 2;
        *(uint32_t*)(out + o) = h;
    }
}

// ---------------------------------------------------------------------------
// fp16 single-product GEMM (measured-best config): C = Ah @ Bh^T (+bias).
// 128x128 tile, BK=64, 256 threads = 8 warps (4x2), warp tile 32x64.
// 3-stage cp.async pipeline, 2 CTAs/SM.
// ---------------------------------------------------------------------------
#define GSTRIDE      144
#define GB_OFF       18432
#define GSTAGE_BYTES 36864
#define GSMEM_BYTES  (3 * GSTAGE_BYTES)

#define GEMM1_BODY                                                            \
    extern __shared__ __align__(1024) char smem[];                            \
    const uint32_t sb = smem_to_u32(smem);                                    \
    const int tid = threadIdx.x;                                              \
    const int wid = tid >> 5, lid = tid & 31;                                 \
    const int wm = wid >> 1;                                                  \
    const int wn = wid & 1;                                                   \
    const uint32_t aBase = (uint32_t)((wm * 32 + (lid & 15)) * GSTRIDE + (lid >> 4) * 16); \
    const uint32_t bBase = (uint32_t)((wn * 64 + ((lid >> 1) & 8) + (lid & 7)) * GSTRIDE \
                                      + ((lid & 8) << 1));                    \
    float acc[2][8][4];                                                       \
    _Pragma("unroll")                                                         \
    for (int mf = 0; mf < 2; mf++)                                            \
        _Pragma("unroll")                                                     \
        for (int nf = 0; nf < 8; nf++)                                        \
            _Pragma("unroll")                                                 \
            for (int q = 0; q < 4; q++) acc[mf][nf][q] = 0.f;                 \
    const int niter = K >> 6;                                                 \
    auto issue = [&](int i, int s) {                                          \
        const int k0 = i << 6;                                                \
        const uint32_t base = sb + s * GSTAGE_BYTES;                          \
        _Pragma("unroll")                                                     \
        for (int j = 0; j < 4; j++) {                                         \
            int c = tid + 256 * j;                                            \
            int row = c >> 3, c8 = c & 7;                                     \
            uint32_t so = (uint32_t)(row * GSTRIDE + c8 * 16);                \
            CP_ASYNC16(base + so,          (const char*)(Ah + (size_t)(m0 + row) * K + k0 + c8 * 8)); \
            CP_ASYNC16(base + GB_OFF + so, (const char*)(Bh + (size_t)(n0 + row) * K + k0 + c8 * 8)); \
        }                                                                     \
    };                                                                        \
    issue(0, 0); CP_COMMIT();                                                 \
    if (niter > 1) { issue(1, 1); CP_COMMIT(); }                              \
    for (int i = 0; i < niter; i++) {                                         \
        const int s = i % 3;                                                  \
        CP_WAIT1();                                                           \
        __syncthreads();                                                      \
        if (i + 2 < niter) issue(i + 2, (i + 2) % 3);                         \
        CP_COMMIT();                                                          \
        const uint32_t sA = sb + s * GSTAGE_BYTES;                            \
        _Pragma("unroll")                                                     \
        for (int kstep = 0; kstep < 4; kstep++) {                             \
            const uint32_t koff = kstep * 32;                                 \
            uint32_t ah[2][4];                                                \
            ldsm4(ah[0], sA + aBase + koff);                                  \
            ldsm4(ah[1], sA + aBase + 16 * GSTRIDE + koff);                   \
            uint32_t bh[8][2];                                                \
            _Pragma("unroll")                                                 \
            for (int t2 = 0; t2 < 4; t2++) {                                  \
                uint32_t r[4];                                                \
                ldsm4(r, sA + GB_OFF + bBase + t2 * 16 * GSTRIDE + koff);     \
                bh[2 * t2][0] = r[0]; bh[2 * t2][1] = r[1];                   \
                bh[2 * t2 + 1][0] = r[2]; bh[2 * t2 + 1][1] = r[3];           \
            }                                                                 \
            _Pragma("unroll")                                                 \
            for (int mf = 0; mf < 2; mf++)                                    \
                _Pragma("unroll")                                             \
                for (int nf = 0; nf < 8; nf++)                                \
                    mma_f16(acc[mf][nf], ah[mf], bh[nf]);                     \
        }                                                                     \
    }                                                                         \
    __syncthreads();

// fp32 output GEMM (output projection)
__global__ __launch_bounds__(256, 2) void gemm1_out_kernel(
    const __half* __restrict__ Ah, const __half* __restrict__ Bh,
    const float* __restrict__ bias, float* __restrict__ C, int N, int K)
{
    const int m0 = blockIdx.y * 128;
    const int n0 = blockIdx.x * 128;
    GEMM1_BODY
    const int erow = m0 + wm * 32 + (lid >> 2);
    const int ecol0 = n0 + wn * 64 + (lid & 3) * 2;
#pragma unroll
    for (int mf = 0; mf < 2; mf++) {
#pragma unroll
        for (int nf = 0; nf < 8; nf++) {
            int col = ecol0 + nf * 8;
            float2 bz = *(const float2*)(bias + col);
            float2 v0, v1;
            v0.x = acc[mf][nf][0] + bz.x; v0.y = acc[mf][nf][1] + bz.y;
            v1.x = acc[mf][nf][2] + bz.x; v1.y = acc[mf][nf][3] + bz.y;
            size_t r0 = (size_t)(erow + mf * 16) * N + col;
            *(float2*)(C + r0) = v0;
            *(float2*)(C + r0 + 8 * N) = v1;
        }
    }
}

// QKV GEMM: single product -> single fp16 plane (Q pre-scaled)
__global__ __launch_bounds__(256, 2) void gemm1_qkv_kernel(
    const __half* __restrict__ Ah, const __half* __restrict__ Bh,
    const float* __restrict__ bias,
    __half* __restrict__ qh, __half* __restrict__ kh, __half* __restrict__ vh,
    int N, int K)
{
    const int m0 = blockIdx.y * 128;
    const int n0 = blockIdx.x * 128;
    GEMM1_BODY
    const int t = n0 >> 11;                 // 0=Q 1=K 2=V
    const int head = (n0 >> 7) & (HEADS - 1);
    __half* p = (t == 0) ? qh : ((t == 1) ? kh : vh);
    const float sc = (t == 0) ? 0.08838834764831845f : 1.0f;
    const int erow = m0 + wm * 32 + (lid >> 2);
    const int lcol0 = wn * 64 + (lid & 3) * 2;
#pragma unroll
    for (int mf = 0; mf < 2; mf++) {
        int tok0 = erow + mf * 16;
        int b = tok0 >> 11;
        int s0 = tok0 & 2047;
        size_t pb = ((size_t)(b * HEADS + head) * S_LEN) * HD;
#pragma unroll
        for (int nf = 0; nf < 8; nf++) {
            int lc = lcol0 + nf * 8;
            float2 bz = *(const float2*)(bias + n0 + lc);
            float v0 = (acc[mf][nf][0] + bz.x) * sc;
            float v1 = (acc[mf][nf][1] + bz.y) * sc;
            float v2 = (acc[mf][nf][2] + bz.x) * sc;
            float v3 = (acc[mf][nf][3] + bz.y) * sc;
            *(uint32_t*)(p + pb + (size_t)s0 * HD + lc)       = packh2(v0, v1);
            *(uint32_t*)(p + pb + (size_t)(s0 + 8) * HD + lc) = packh2(v2, v3);
        }
    }
}

// ---------------------------------------------------------------------------
// Tensor-core flash attention (fp16), Q tile = 128 rows, warp-local softmax.
// 2-stage K/V cp.async pipeline, 2 CTAs/SM, per-warp skip + fast path.
// 1D grid (1024): GLOBAL big-tile-first schedule:
//   qt = 15 - bx/64 (all 64 (h,b) of the largest tile first), hb = bx % 64.
// ---------------------------------------------------------------------------
#define AQ_STRIDE 272                 // smem bytes per row (128 fp16 + pad)
#define SQH 0                         // 128 * 272 = 34816
#define SSTAGE0 34816
#define SSTAGE_BYTES 34816            // Kh (17408) + Vh (17408)
#define SKH 0
#define SVH 17408
#define SKID  104448                  // + stage*256 (2 stages)
#define ATTN_SMEM 105472

__global__ __launch_bounds__(256, 2) void attn_mma_kernel(
    const int* __restrict__ ids,
    __half* __restrict__ oh,
    const __half* __restrict__ qh,
    const __half* __restrict__ kh, const __half* __restrict__ vh)
{
    extern __shared__ __align__(1024) char smem[];
    const uint32_t sb = smem_to_u32(smem);
    const int tid = threadIdx.x;
    const int lane = tid & 31, wid = tid >> 5;
    // global big-tile-first mapping
    const int qt = (S_LEN / 128 - 1) - (blockIdx.x >> 6);
    const int hb = blockIdx.x & 63;
    const int h = hb & (HEADS - 1);
    const int b = hb >> 4;
    const int q0 = qt * 128;
    const size_t pbase = (size_t)(b * HEADS + h) * S_LEN * HD;
    const int* bids = ids + b * S_LEN;

    const int lr = lane >> 2;
    const int row0 = wid * 16 + lr, row1 = row0 + 8;
    const int qrow0 = q0 + row0, qrow1 = q0 + row1;
    const int qidv0 = bids[qrow0], qidv1 = bids[qrow1];
    const int qid_min = bids[q0];

    const int qwmin = q0 + wid * 16;                 // warp's first q row
    const int idq0 = bids[qwmin];
    const int idq15 = bids[qwmin + 15];
    const bool seg_uni_q = (idq0 == idq15);

    auto issue_tile = [&](int kb, int s) {
        const int k0 = kb * 64;
        const uint32_t stg = sb + SSTAGE0 + s * SSTAGE_BYTES;
#pragma unroll
        for (int j = 0; j < 4; j++) {
            int q = tid + 256 * j;
            int key = q >> 4, c16 = q & 15;
            uint32_t soff = (uint32_t)(key * AQ_STRIDE + c16 * 16);
            size_t goff = pbase + (size_t)(k0 + key) * HD + c16 * 8;
            CP_ASYNC16(stg + SKH + soff, (const char*)(kh + goff));
            CP_ASYNC16(stg + SVH + soff, (const char*)(vh + goff));
        }
        if (tid < 16)
            CP_ASYNC16(sb + SKID + s * 256 + tid * 16,
                       (const char*)(bids + k0 + tid * 4));
    };

    const int nkb = 2 * qt + 1;

    // ---- prologue: Q tile (128 rows) + tile 0 in group 0, tile 1 in group 1
#pragma unroll
    for (int j = 0; j < 8; j++) {
        int q = tid + 256 * j;
        int key = q >> 4, c16 = q & 15;
        uint32_t soff = (uint32_t)(key * AQ_STRIDE + c16 * 16);
        size_t goff = pbase + (size_t)(q0 + key) * HD + c16 * 8;
        CP_ASYNC16(sb + SQH + soff, (const char*)(qh + goff));
    }
    if (bids[63] >= qid_min) issue_tile(0, 0);
    CP_COMMIT();
    if (bids[127] >= qid_min) issue_tile(1, 1);
    CP_COMMIT();

    float O[16][4];
#pragma unroll
    for (int nb = 0; nb < 16; nb++)
#pragma unroll
        for (int q = 0; q < 4; q++) O[nb][q] = 0.f;
    float m0r = -1e30f, m1r = -1e30f, l0r = 0.f, l1r = 0.f;

    const uint32_t qoffA = (uint32_t)((wid * 16 + (lane & 15)) * AQ_STRIDE + (lane >> 4) * 16);
    const uint32_t kBoff = (uint32_t)((((lane >> 1) & 8) + (lane & 7)) * AQ_STRIDE
                                      + ((lane & 8) << 1));
    const uint32_t vBoff = (uint32_t)((((lane >> 3) & 1) * 8 + (lane & 7)) * AQ_STRIDE
                                      + ((lane >> 4) & 1) * 16);

    for (int kb = 0; kb <= nkb; kb++) {
        const int s = kb & 1;
        CP_WAIT1();
        __syncthreads();

        const int k0 = kb * 64;
        const int kidlo = bids[k0];
        const int kidhi = bids[k0 + 63];
        const bool skip = (kidhi < qid_min) || (kidhi < idq0);

        if (!skip) {
            const uint32_t stg = sb + SSTAGE0 + s * SSTAGE_BYTES;

            // ---- S = Q·K^T over 64 keys (8 n-frags) ----
            float S[8][4];
#pragma unroll
            for (int nf = 0; nf < 8; nf++)
#pragma unroll
                for (int c = 0; c < 4; c++) S[nf][c] = 0.f;
#pragma unroll
            for (int ks = 0; ks < 8; ks++) {
                uint32_t ah[4];
                ldsm4(ah, sb + SQH + qoffA + ks * 32);
#pragma unroll
                for (int kf = 0; kf < 4; kf++) {
                    uint32_t khf[4];
                    ldsm4(khf, stg + SKH + kBoff + kf * 16 * AQ_STRIDE + ks * 32);
                    mma_f16(S[2 * kf],     ah, khf + 0);
                    mma_f16(S[2 * kf + 1], ah, khf + 2);
                }
            }

            const bool fast = seg_uni_q && (kidlo == kidhi) && (kidlo == idq0)
                              && (k0 + 63 <= qwmin);

            float mt0 = -1e30f, mt1 = -1e30f;
            if (fast) {
#pragma unroll
                for (int nf = 0; nf < 8; nf++) {
                    mt0 = fmaxf(mt0, fmaxf(S[nf][0], S[nf][1]));
                    mt1 = fmaxf(mt1, fmaxf(S[nf][2], S[nf][3]));
                }
            } else {
                const uint32_t kidb = sb + SKID + s * 256;
#pragma unroll
                for (int nf = 0; nf < 8; nf++) {
                    int lc = nf * 8 + 2 * (lane & 3);
                    int kv0, kv1;
                    asm volatile("ld.shared.v2.u32 {%0,%1}, [%2];"
                                 : "=r"(kv0), "=r"(kv1) : "r"(kidb + lc * 4));
                    int key = k0 + lc;
                    if (key     > qrow0 || kv0 != qidv0) S[nf][0] = -1e30f;
                    if (key + 1 > qrow0 || kv1 != qidv0) S[nf][1] = -1e30f;
                    if (key     > qrow1 || kv0 != qidv1) S[nf][2] = -1e30f;
                    if (key + 1 > qrow1 || kv1 != qidv1) S[nf][3] = -1e30f;
                    mt0 = fmaxf(mt0, fmaxf(S[nf][0], S[nf][1]));
                    mt1 = fmaxf(mt1, fmaxf(S[nf][2], S[nf][3]));
                }
            }
            mt0 = fmaxf(mt0, __shfl_xor_sync(0xffffffffu, mt0, 1));
            mt0 = fmaxf(mt0, __shfl_xor_sync(0xffffffffu, mt0, 2));
            mt1 = fmaxf(mt1, __shfl_xor_sync(0xffffffffu, mt1, 1));
            mt1 = fmaxf(mt1, __shfl_xor_sync(0xffffffffu, mt1, 2));

            float mn0 = fmaxf(m0r, mt0);
            float mn1 = fmaxf(m1r, mt1);
            float f0 = __expf(m0r - mn0), f1 = __expf(m1r - mn1);
            m0r = mn0; m1r = mn1;

            float rs0 = 0.f, rs1 = 0.f;
            if (fast) {
#pragma unroll
                for (int nf = 0; nf < 8; nf++) {
                    float p0 = __expf(S[nf][0] - mn0);
                    float p1 = __expf(S[nf][1] - mn0);
                    float p2 = __expf(S[nf][2] - mn1);
                    float p3 = __expf(S[nf][3] - mn1);
                    S[nf][0] = p0; S[nf][1] = p1; S[nf][2] = p2; S[nf][3] = p3;
                    rs0 += p0 + p1; rs1 += p2 + p3;
                }
            } else {
#pragma unroll
                for (int nf = 0; nf < 8; nf++) {
                    float p0 = (S[nf][0] < -1e29f) ? 0.f : __expf(S[nf][0] - mn0);
                    float p1 = (S[nf][1] < -1e29f) ? 0.f : __expf(S[nf][1] - mn0);
                    float p2 = (S[nf][2] < -1e29f) ? 0.f : __expf(S[nf][2] - mn1);
                    float p3 = (S[nf][3] < -1e29f) ? 0.f : __expf(S[nf][3] - mn1);
                    S[nf][0] = p0; S[nf][1] = p1; S[nf][2] = p2; S[nf][3] = p3;
                    rs0 += p0 + p1; rs1 += p2 + p3;
                }
            }
            rs0 += __shfl_xor_sync(0xffffffffu, rs0, 1);
            rs0 += __shfl_xor_sync(0xffffffffu, rs0, 2);
            rs1 += __shfl_xor_sync(0xffffffffu, rs1, 1);
            rs1 += __shfl_xor_sync(0xffffffffu, rs1, 2);
            l0r = l0r * f0 + rs0;
            l1r = l1r * f1 + rs1;

            // rescale O
#pragma unroll
            for (int nb = 0; nb < 16; nb++) {
                O[nb][0] *= f0; O[nb][1] *= f0;
                O[nb][2] *= f1; O[nb][3] *= f1;
            }

            // ---- O += RN16(P)·V over the 64-key dim (4 k16 chunks) ----
#pragma unroll
            for (int ks2 = 0; ks2 < 4; ks2++) {
                uint32_t ah[4];
                ah[0] = packh2(S[2 * ks2][0],     S[2 * ks2][1]);
                ah[1] = packh2(S[2 * ks2][2],     S[2 * ks2][3]);
                ah[2] = packh2(S[2 * ks2 + 1][0], S[2 * ks2 + 1][1]);
                ah[3] = packh2(S[2 * ks2 + 1][2], S[2 * ks2 + 1][3]);
                uint32_t ro = vBoff + ks2 * 16 * AQ_STRIDE;
#pragma unroll
                for (int np = 0; np < 4; np++) {
                    uint32_t vh0[4], vh1[4];
                    ldsm4t(vh0, stg + SVH + ro + (2 * np) * 32);
                    ldsm4t(vh1, stg + SVH + ro + (2 * np + 1) * 32);
                    int o0 = 4 * np;
                    mma_f16(O[o0 + 0], ah, vh0 + 0); mma_f16(O[o0 + 1], ah, vh0 + 2);
                    mma_f16(O[o0 + 2], ah, vh1 + 0); mma_f16(O[o0 + 3], ah, vh1 + 2);
                }
            }
        }

        // stage s is free only after every warp finished reading it
        __syncthreads();
        if (kb + 2 <= nkb) {
            if (bids[(kb + 2) * 64 + 63] >= qid_min) issue_tile(kb + 2, s);
        }
        CP_COMMIT();
    }

    // ---- epilogue: warp-local normalize, write fp16 plane directly ----
    float inv0 = 1.f / l0r;
    float inv1 = 1.f / l1r;
    const size_t g0 = ((size_t)b * S_LEN + qrow0) * DIM + h * HD;
    const size_t g1 = ((size_t)b * S_LEN + qrow1) * DIM + h * HD;
#pragma unroll
    for (int nb = 0; nb < 16; nb++) {
        int col = nb * 8 + 2 * (lane & 3);
        *(uint32_t*)(oh + g0 + col) = packh2(O[nb][0] * inv0, O[nb][1] * inv0);
        *(uint32_t*)(oh + g1 + col) = packh2(O[nb][2] * inv1, O[nb][3] * inv1);
    }
}

// ---------------------------------------------------------------------------
extern "C" void kernel_launch(void* const* d_in, const int* in_sizes, int n_in,
                              void* d_out, int out_size)
{
    const float* x    = (const float*)d_in[0];   // [4,2048,2048]
    const int*   ids  = (const int*)d_in[1];     // [4,2048]
    const float* Wqkv = (const float*)d_in[2];   // [2048,6144]
    const float* bqkv = (const float*)d_in[3];   // [6144]
    const float* Wo   = (const float*)d_in[4];   // [2048,2048]
    const float* bo   = (const float*)d_in[5];   // [2048]
    float* out = (float*)d_out;

    __half *qh, *kh, *vh, *xh, *ah, *wqh, *woh;
    cudaGetSymbolAddress((void**)&qh, g_qh);
    cudaGetSymbolAddress((void**)&kh, g_kh);
    cudaGetSymbolAddress((void**)&vh, g_vh);
    cudaGetSymbolAddress((void**)&xh, g_xh);
    cudaGetSymbolAddress((void**)&ah, g_ah);
    cudaGetSymbolAddress((void**)&wqh, g_wqh);
    cudaGetSymbolAddress((void**)&woh, g_woh);

    cudaFuncSetAttribute(gemm1_out_kernel,
                         cudaFuncAttributeMaxDynamicSharedMemorySize, GSMEM_BYTES);
    cudaFuncSetAttribute(gemm1_qkv_kernel,
                         cudaFuncAttributeMaxDynamicSharedMemorySize, GSMEM_BYTES);
    cudaFuncSetAttribute(attn_mma_kernel,
                         cudaFuncAttributeMaxDynamicSharedMemorySize, ATTN_SMEM);

    const int M = BATCH * S_LEN;   // 8192

    // 0) round x, round+transpose weights (one-shot)
    round_kernel<<<1184, 256>>>(x, xh, (size_t)M * DIM / 2);
    {
        dim3 blk(32, 8);
        transpose_round_kernel<<<dim3(3 * DIM / 32, DIM / 32), blk>>>(Wqkv, wqh, DIM, 3 * DIM);
        transpose_round_kernel<<<dim3(DIM / 32, DIM / 32), blk>>>(Wo, woh, DIM, DIM);
    }
    // 1) QKV = x @ Wqkv + bqkv -> fp16 planes (Q pre-scaled), single product
    {
        dim3 grid(3 * DIM / 128, M / 128);
        gemm1_qkv_kernel<<<grid, 256, GSMEM_BYTES>>>(
            xh, wqh, bqkv, qh, kh, vh, 3 * DIM, DIM);
    }
    // 2) flash attention -> single fp16 plane (1D grid, global big-first)
    {
        attn_mma_kernel<<<(S_LEN / 128) * HEADS * BATCH, 256, ATTN_SMEM>>>(
            ids, ah, qh, kh, vh);
    }
    // 3) out = attn @ Wo + bo  [8192, 2048] fp32, single product
    {
        dim3 grid(DIM / 128, M / 128);
        gemm1_out_kernel<<<grid, 256, GSMEM_BYTES>>>(ah, woh, bo, out, DIM, DIM);
    }
}